// round 2
// baseline (speedup 1.0000x reference)
#include <cuda_runtime.h>
#include <cstdint>

#define NN 50000
#define NE 800000
#define F 128
#define NC 16

// ---------------- scratch (static device globals; no allocs) ----------------
__device__ float g_h1[(size_t)NN * F];   // X@W_self1 + b1, later relu(result)
__device__ float g_nb[(size_t)NN * F];   // X@W_neigh1 (projected neighbor feats)
__device__ float g_D [(size_t)NN * NC];  // h1@W_neigh2
__device__ int   g_deg[NN];
__device__ int   g_cur[NN];
__device__ int   g_rowoff[NN + 1];
__device__ int   g_esrc[NE];
__device__ int   g_is64;                 // 1 if src/dst are int64, 0 if int32

// ---------------- dtype detection ----------------
// If the index buffers are int64 (little-endian, values < 50000), every odd
// 32-bit word is zero. For int32 data the odd words are node indices in
// [0, 50000) and are essentially never all zero over 256 samples.
__global__ void detect_k(const int* __restrict__ dst32) {
    if (threadIdx.x == 0) {
        int all_zero = 1;
        for (int i = 0; i < 256; i++)
            if (dst32[2 * i + 1] != 0) { all_zero = 0; break; }
        g_is64 = all_zero;
    }
}

__device__ __forceinline__ int load_idx(const void* p, int i) {
    if (g_is64) return (int)((const long long*)p)[i];
    return ((const int*)p)[i];
}

// ---------------- CSR build ----------------
__global__ void zero_k() {
    int i = blockIdx.x * blockDim.x + threadIdx.x;
    if (i < NN) { g_deg[i] = 0; g_cur[i] = 0; }
}

__global__ void count_k(const void* __restrict__ dst) {
    int i = blockIdx.x * blockDim.x + threadIdx.x;
    if (i < NE) {
        int d = load_idx(dst, i);
        if (d >= 0 && d < NN) atomicAdd(&g_deg[d], 1);
    }
}

__global__ void scan_k() {
    __shared__ int sh[1024];
    __shared__ int carry_s;
    int tid = threadIdx.x;
    if (tid == 0) { carry_s = 0; g_rowoff[0] = 0; }
    __syncthreads();
    for (int base = 0; base < NN; base += 1024) {
        int i = base + tid;
        int v = (i < NN) ? g_deg[i] : 0;
        sh[tid] = v;
        __syncthreads();
        for (int off = 1; off < 1024; off <<= 1) {
            int t = (tid >= off) ? sh[tid - off] : 0;
            __syncthreads();
            sh[tid] += t;
            __syncthreads();
        }
        int carry = carry_s;
        if (i < NN) g_rowoff[i + 1] = carry + sh[tid];
        __syncthreads();
        if (tid == 1023) carry_s = carry + sh[1023];
        __syncthreads();
    }
}

__global__ void fill_k(const void* __restrict__ src,
                       const void* __restrict__ dst) {
    int i = blockIdx.x * blockDim.x + threadIdx.x;
    if (i < NE) {
        int d = load_idx(dst, i);
        int s = load_idx(src, i);
        if (d < 0 || d >= NN || s < 0 || s >= NN) return;
        int pos = atomicAdd(&g_cur[d], 1);
        int off = g_rowoff[d] + pos;
        if (off < NE) g_esrc[off] = s;
    }
}

// ---------------- fp32 tile GEMM: Y[M,N] = X[M,128] @ W[128,N] (+bias) ------
// BM=64, BN=64, BK=16, 256 threads, 4x4 per thread. N must be multiple of 64.
__global__ void gemm_nn(const float* __restrict__ X, const float* __restrict__ W,
                        const float* __restrict__ bias, float* __restrict__ Y,
                        int M, int N)
{
    __shared__ float As[16][68];
    __shared__ float Bs[16][64];
    int tid = threadIdx.x;
    int tx = tid & 15, ty = tid >> 4;
    int rowBase = blockIdx.y * 64;
    int colBase = blockIdx.x * 64;

    float acc[4][4] = {};

    int la_k = tid & 15;   // As load: k index
    int la_m = tid >> 4;   // As load: m base (stride 16, 4 loads)
    int lb_n = tid & 63;   // Bs load: n index
    int lb_k = tid >> 6;   // Bs load: k base (stride 4, 4 loads)

    for (int k0 = 0; k0 < 128; k0 += 16) {
#pragma unroll
        for (int j = 0; j < 4; j++) {
            int m = la_m + j * 16;
            int r = rowBase + m;
            As[la_k][m] = (r < M) ? X[(size_t)r * 128 + k0 + la_k] : 0.f;
        }
#pragma unroll
        for (int j = 0; j < 4; j++) {
            int k = lb_k + j * 4;
            Bs[k][lb_n] = W[(size_t)(k0 + k) * N + colBase + lb_n];
        }
        __syncthreads();
#pragma unroll
        for (int k = 0; k < 16; k++) {
            float a[4], b[4];
#pragma unroll
            for (int i = 0; i < 4; i++) a[i] = As[k][ty * 4 + i];
#pragma unroll
            for (int i = 0; i < 4; i++) b[i] = Bs[k][tx * 4 + i];
#pragma unroll
            for (int i = 0; i < 4; i++)
#pragma unroll
                for (int j = 0; j < 4; j++)
                    acc[i][j] += a[i] * b[j];
        }
        __syncthreads();
    }
#pragma unroll
    for (int i = 0; i < 4; i++) {
        int r = rowBase + ty * 4 + i;
        if (r >= M) continue;
#pragma unroll
        for (int j = 0; j < 4; j++) {
            int c = colBase + tx * 4 + j;
            float v = acc[i][j];
            if (bias) v += bias[c];
            Y[(size_t)r * N + c] = v;
        }
    }
}

// ---------------- layer-1 aggregate + combine + relu ----------------
// one warp per node; each lane owns a float4 (128 floats / 32 lanes)
__global__ void agg1_k() {
    int gwarp = (blockIdx.x * blockDim.x + threadIdx.x) >> 5;
    if (gwarp >= NN) return;
    int lane = threadIdx.x & 31;
    int beg = g_rowoff[gwarp], end = g_rowoff[gwarp + 1];
    float4 s = make_float4(0.f, 0.f, 0.f, 0.f);
    for (int e = beg; e < end; e++) {
        int sn = g_esrc[e];
        float4 v = reinterpret_cast<const float4*>(g_nb + (size_t)sn * F)[lane];
        s.x += v.x; s.y += v.y; s.z += v.z; s.w += v.w;
    }
    float inv = 1.0f / fmaxf((float)(end - beg), 1.0f);
    float4* hp = reinterpret_cast<float4*>(g_h1 + (size_t)gwarp * F);
    float4 a = hp[lane];
    a.x = fmaxf(a.x + s.x * inv, 0.f);
    a.y = fmaxf(a.y + s.y * inv, 0.f);
    a.z = fmaxf(a.z + s.z * inv, 0.f);
    a.w = fmaxf(a.w + s.w * inv, 0.f);
    hp[lane] = a;
}

// ---------------- layer-2 GEMM: out = h1@W_self2 + b2 ; D = h1@W_neigh2 -----
// 256 threads = 8 rows x 32 cols (cols 0..15 -> self, 16..31 -> neigh)
__global__ void gemm2_k(const float* __restrict__ Ws, const float* __restrict__ Wn,
                        const float* __restrict__ b2, float* __restrict__ out)
{
    __shared__ float Xs[8][132];
    __shared__ float Wsh[128][32];
    int tid = threadIdx.x;
    for (int i = tid; i < 128 * 32; i += 256) {
        int k = i >> 5, c = i & 31;
        Wsh[k][c] = (c < 16) ? Ws[k * 16 + c] : Wn[k * 16 + (c - 16)];
    }
    int rowBase = blockIdx.x * 8;
    for (int i = tid; i < 8 * 128; i += 256) {
        int r = i >> 7, k = i & 127;
        int gr = rowBase + r;
        Xs[r][k] = (gr < NN) ? g_h1[(size_t)gr * 128 + k] : 0.f;
    }
    __syncthreads();
    int r = tid >> 5, c = tid & 31;
    float acc = 0.f;
#pragma unroll 16
    for (int k = 0; k < 128; k++) acc += Xs[r][k] * Wsh[k][c];
    int gr = rowBase + r;
    if (gr < NN) {
        if (c < 16) out[(size_t)gr * NC + c] = acc + b2[c];
        else        g_D[(size_t)gr * NC + (c - 16)] = acc;
    }
}

// ---------------- layer-2 aggregate + add ----------------
// 16 threads per node, one dim each
__global__ void agg2_k(float* __restrict__ out) {
    int idx = blockIdx.x * blockDim.x + threadIdx.x;
    int node = idx >> 4;
    if (node >= NN) return;
    int dim = idx & 15;
    int beg = g_rowoff[node], end = g_rowoff[node + 1];
    float s = 0.f;
    for (int e = beg; e < end; e++)
        s += g_D[(size_t)g_esrc[e] * NC + dim];
    float inv = 1.0f / fmaxf((float)(end - beg), 1.0f);
    out[(size_t)node * NC + dim] += s * inv;
}

// ---------------- launch ----------------
extern "C" void kernel_launch(void* const* d_in, const int* in_sizes, int n_in,
                              void* d_out, int out_size)
{
    const float* in_feat = (const float*)d_in[0];
    const void*  src     = d_in[1];
    const void*  dst     = d_in[2];
    const float* Wself1  = (const float*)d_in[3];
    const float* Wneigh1 = (const float*)d_in[4];
    const float* b1      = (const float*)d_in[5];
    const float* Wself2  = (const float*)d_in[6];
    const float* Wneigh2 = (const float*)d_in[7];
    const float* b2      = (const float*)d_in[8];
    float* out = (float*)d_out;

    float *p_h1 = nullptr, *p_nb = nullptr;
    cudaGetSymbolAddress((void**)&p_h1, g_h1);
    cudaGetSymbolAddress((void**)&p_nb, g_nb);

    // dtype detection + CSR build
    detect_k<<<1, 32>>>((const int*)dst);
    zero_k <<<(NN + 255) / 256, 256>>>();
    count_k<<<(NE + 255) / 256, 256>>>(dst);
    scan_k <<<1, 1024>>>();
    fill_k <<<(NE + 255) / 256, 256>>>(src, dst);

    // layer 1: projections
    dim3 g1(128 / 64, (NN + 63) / 64);
    gemm_nn<<<g1, 256>>>(in_feat, Wself1, b1, p_h1, NN, 128);
    gemm_nn<<<g1, 256>>>(in_feat, Wneigh1, nullptr, p_nb, NN, 128);

    // layer 1: aggregate + combine + relu (h1 in place)
    agg1_k<<<(NN * 32 + 255) / 256, 256>>>();

    // layer 2: projections (out gets self part + bias, g_D gets neigh part)
    gemm2_k<<<(NN + 7) / 8, 256>>>(Wself2, Wneigh2, b2, out);

    // layer 2: aggregate + add
    agg2_k<<<(NN * 16 + 255) / 256, 256>>>(out);
}

// round 5
// speedup vs baseline: 1.1460x; 1.1460x over previous
#include <cuda_runtime.h>
#include <cuda_bf16.h>
#include <cstdint>

#define NN 50000
#define NE 800000
#define F 128
#define NC 16
#define NBLK 196   // 196*256 = 50176 >= NN

// ---------------- scratch (static device globals; no allocs) ----------------
__device__ float g_h1[(size_t)NN * F];   // layer1 self-proj + b1 -> relu(h1)
__device__ float g_nb[(size_t)NN * F];   // layer1 neigh-proj
__device__ float g_D [(size_t)NN * NC];  // h1@W_neigh2
__device__ int   g_deg[NN];
__device__ int   g_cur[NN];
__device__ int   g_rowoff[NN + 1];
__device__ int   g_esrc[NE];
__device__ int   g_part[NBLK * 256];
__device__ int   g_bsum[NBLK];
__device__ int   g_boff[NBLK];
__device__ int   g_is64;
// bf16 hi/lo split operands for tensor GEMM
__device__ __nv_bfloat16 g_xhi[(size_t)NN * F];
__device__ __nv_bfloat16 g_xlo[(size_t)NN * F];
__device__ __nv_bfloat16 g_wThi[2 * F * F];  // [mat][n][k] = W[k][n]
__device__ __nv_bfloat16 g_wTlo[2 * F * F];

// ---------------- helpers ----------------
__device__ __forceinline__ uint32_t smem_u32(const void* p) {
    uint32_t a;
    asm("{ .reg .u64 t; cvta.to.shared.u64 t, %1; cvt.u32.u64 %0, t; }"
        : "=r"(a) : "l"(p));
    return a;
}
__device__ __forceinline__ void ldm_x4(uint32_t* r, uint32_t addr) {
    asm volatile("ldmatrix.sync.aligned.m8n8.x4.shared.b16 {%0,%1,%2,%3}, [%4];"
                 : "=r"(r[0]), "=r"(r[1]), "=r"(r[2]), "=r"(r[3]) : "r"(addr));
}
__device__ __forceinline__ void ldm_x2(uint32_t* r, uint32_t addr) {
    asm volatile("ldmatrix.sync.aligned.m8n8.x2.shared.b16 {%0,%1}, [%2];"
                 : "=r"(r[0]), "=r"(r[1]) : "r"(addr));
}
__device__ __forceinline__ void mma16816(float* d, const uint32_t* a, const uint32_t* b) {
    asm volatile("mma.sync.aligned.m16n8k16.row.col.f32.bf16.bf16.f32 "
                 "{%0,%1,%2,%3}, {%4,%5,%6,%7}, {%8,%9}, {%0,%1,%2,%3};"
                 : "+f"(d[0]), "+f"(d[1]), "+f"(d[2]), "+f"(d[3])
                 : "r"(a[0]), "r"(a[1]), "r"(a[2]), "r"(a[3]), "r"(b[0]), "r"(b[1]));
}

// ---------------- dtype detection ----------------
__global__ void detect_k(const int* __restrict__ dst32) {
    if (threadIdx.x == 0) {
        int all_zero = 1;
        for (int i = 0; i < 256; i++)
            if (dst32[2 * i + 1] != 0) { all_zero = 0; break; }
        g_is64 = all_zero;
    }
}
__device__ __forceinline__ int load_idx(const void* p, int i) {
    if (g_is64) return (int)((const long long*)p)[i];
    return ((const int*)p)[i];
}

// ---------------- CSR build ----------------
__global__ void zero_k() {
    int i = blockIdx.x * blockDim.x + threadIdx.x;
    if (i < NN) { g_deg[i] = 0; g_cur[i] = 0; }
}
__global__ void count_k(const void* __restrict__ dst) {
    int i = blockIdx.x * blockDim.x + threadIdx.x;
    if (i < NE) {
        int d = load_idx(dst, i);
        if (d >= 0 && d < NN) atomicAdd(&g_deg[d], 1);
    }
}
__global__ void scanA_k() {
    __shared__ int sh[256];
    int t = threadIdx.x, i = blockIdx.x * 256 + t;
    int v = (i < NN) ? g_deg[i] : 0;
    sh[t] = v;
    __syncthreads();
#pragma unroll
    for (int off = 1; off < 256; off <<= 1) {
        int u = (t >= off) ? sh[t - off] : 0;
        __syncthreads();
        sh[t] += u;
        __syncthreads();
    }
    g_part[i] = sh[t];
    if (t == 255) g_bsum[blockIdx.x] = sh[255];
}
__global__ void scanB_k() {
    __shared__ int sh[256];
    int t = threadIdx.x;
    int v = (t < NBLK) ? g_bsum[t] : 0;
    sh[t] = v;
    __syncthreads();
#pragma unroll
    for (int off = 1; off < 256; off <<= 1) {
        int u = (t >= off) ? sh[t - off] : 0;
        __syncthreads();
        sh[t] += u;
        __syncthreads();
    }
    if (t < NBLK) g_boff[t] = sh[t] - v;  // exclusive
}
__global__ void scanC_k() {
    int i = blockIdx.x * blockDim.x + threadIdx.x;
    if (i < NN) {
        g_rowoff[i + 1] = g_part[i] + g_boff[i >> 8];
        if (i == 0) g_rowoff[0] = 0;
    }
}
__global__ void fill_k(const void* __restrict__ src, const void* __restrict__ dst) {
    int i = blockIdx.x * blockDim.x + threadIdx.x;
    if (i < NE) {
        int d = load_idx(dst, i);
        int s = load_idx(src, i);
        if (d < 0 || d >= NN || s < 0 || s >= NN) return;
        int pos = atomicAdd(&g_cur[d], 1);
        int off = g_rowoff[d] + pos;
        if (off < NE) g_esrc[off] = s;
    }
}

// ---------------- bf16 hi/lo conversions ----------------
__global__ void convx_k(const float* __restrict__ x) {
    int i = blockIdx.x * blockDim.x + threadIdx.x;      // handles 4 floats
    if (i >= NN * F / 4) return;
    float4 v = reinterpret_cast<const float4*>(x)[i];
    __nv_bfloat16 hx = __float2bfloat16(v.x), hy = __float2bfloat16(v.y);
    __nv_bfloat16 hz = __float2bfloat16(v.z), hw = __float2bfloat16(v.w);
    __nv_bfloat16 lx = __float2bfloat16(v.x - __bfloat162float(hx));
    __nv_bfloat16 ly = __float2bfloat16(v.y - __bfloat162float(hy));
    __nv_bfloat16 lz = __float2bfloat16(v.z - __bfloat162float(hz));
    __nv_bfloat16 lw = __float2bfloat16(v.w - __bfloat162float(hw));
    reinterpret_cast<__nv_bfloat162*>(g_xhi)[2 * i]     = __nv_bfloat162(hx, hy);
    reinterpret_cast<__nv_bfloat162*>(g_xhi)[2 * i + 1] = __nv_bfloat162(hz, hw);
    reinterpret_cast<__nv_bfloat162*>(g_xlo)[2 * i]     = __nv_bfloat162(lx, ly);
    reinterpret_cast<__nv_bfloat162*>(g_xlo)[2 * i + 1] = __nv_bfloat162(lz, lw);
}
__global__ void convw_k(const float* __restrict__ Ws, const float* __restrict__ Wn) {
    int i = blockIdx.x * blockDim.x + threadIdx.x;      // [mat][n][k]
    if (i >= 2 * F * F) return;
    int mat = i >> 14, n = (i >> 7) & 127, k = i & 127;
    float w = (mat == 0) ? Ws[k * F + n] : Wn[k * F + n];
    __nv_bfloat16 h = __float2bfloat16(w);
    g_wThi[i] = h;
    g_wTlo[i] = __float2bfloat16(w - __bfloat162float(h));
}

// ---------------- layer-1 GEMM via mma.sync (bf16 hi/lo, fp32 acc) ----------
// Y[128tile,128] = X[128,128] @ W[128,128]; 3 terms: Ahi*Bhi + Alo*Bhi + Ahi*Blo
// blockIdx.x: mat (0 -> g_h1 + b1, 1 -> g_nb), blockIdx.y: row tile.
// 512 threads = 16 warps, warp grid 4x4, warp tile 32x32.
#define RS 136                       // smem row stride in bf16 (136*2=272B)
#define TILE_B (128 * RS * 2)        // 34816 bytes per buffer
#define OFF_AHI 0
#define OFF_ALO (TILE_B)
#define OFF_BHI (2 * TILE_B)
#define OFF_BLO (3 * TILE_B)
#define SMEM_G1 (4 * TILE_B)

__global__ void __launch_bounds__(512, 1)
gemm1_mma(const float* __restrict__ b1) {
    extern __shared__ char smem[];
    uint32_t sb = smem_u32(smem);
    int tid = threadIdx.x, wid = tid >> 5, lane = tid & 31;
    int rowBase = blockIdx.y * 128;
    int mat = blockIdx.x;
    const __nv_bfloat16* wthi = g_wThi + (size_t)mat * F * F;
    const __nv_bfloat16* wtlo = g_wTlo + (size_t)mat * F * F;

    // ---- stage tiles: uint4 = 8 bf16 per store; 128 rows x 16 chunks ----
    for (int i = tid; i < 128 * 16; i += 512) {
        int r = i >> 4, cc = i & 15;        // chunk index (16 bytes each)
        uint32_t so = (uint32_t)r * (RS * 2) + cc * 16;
        int gr = rowBase + r;
        uint4 vh = make_uint4(0, 0, 0, 0), vl = make_uint4(0, 0, 0, 0);
        if (gr < NN) {
            vh = reinterpret_cast<const uint4*>(g_xhi + (size_t)gr * F)[cc];
            vl = reinterpret_cast<const uint4*>(g_xlo + (size_t)gr * F)[cc];
        }
        *reinterpret_cast<uint4*>(smem + OFF_AHI + so) = vh;
        *reinterpret_cast<uint4*>(smem + OFF_ALO + so) = vl;
        *reinterpret_cast<uint4*>(smem + OFF_BHI + so) =
            reinterpret_cast<const uint4*>(wthi + (size_t)r * F)[cc];
        *reinterpret_cast<uint4*>(smem + OFF_BLO + so) =
            reinterpret_cast<const uint4*>(wtlo + (size_t)r * F)[cc];
    }
    __syncthreads();

    int wm = (wid & 3) * 32;   // warp row offset
    int wn = (wid >> 2) * 32;  // warp col offset

    float acc[2][4][4];
#pragma unroll
    for (int mt = 0; mt < 2; mt++)
#pragma unroll
        for (int nt = 0; nt < 4; nt++)
#pragma unroll
            for (int e = 0; e < 4; e++) acc[mt][nt][e] = 0.f;

    // ldmatrix addresses (byte offsets into row-major [r][RS] bf16)
    uint32_t a_row = wm + (lane & 15);
    uint32_t a_coff = (lane >> 4) * 16;                // bytes
    uint32_t b_row = wn + (lane & 7);
    uint32_t b_coff = ((lane >> 3) & 1) * 16;          // bytes

#pragma unroll
    for (int ks = 0; ks < 8; ks++) {
        uint32_t kb = ks * 32;                         // 16 halves = 32 bytes
        uint32_t ahi[2][4], alo[2][4], bhi[4][2], blo[4][2];
#pragma unroll
        for (int mt = 0; mt < 2; mt++) {
            uint32_t ro = (a_row + mt * 16) * (RS * 2) + kb + a_coff;
            ldm_x4(ahi[mt], sb + OFF_AHI + ro);
            ldm_x4(alo[mt], sb + OFF_ALO + ro);
        }
#pragma unroll
        for (int nt = 0; nt < 4; nt++) {
            uint32_t ro = (b_row + nt * 8) * (RS * 2) + kb + b_coff;
            ldm_x2(bhi[nt], sb + OFF_BHI + ro);
            ldm_x2(blo[nt], sb + OFF_BLO + ro);
        }
#pragma unroll
        for (int mt = 0; mt < 2; mt++)
#pragma unroll
            for (int nt = 0; nt < 4; nt++) {
                mma16816(acc[mt][nt], ahi[mt], bhi[nt]);
                mma16816(acc[mt][nt], alo[mt], bhi[nt]);
                mma16816(acc[mt][nt], ahi[mt], blo[nt]);
            }
    }

    // ---- epilogue ----
    float* outp = (mat == 0) ? g_h1 : g_nb;
#pragma unroll
    for (int mt = 0; mt < 2; mt++) {
        int r0 = rowBase + wm + mt * 16 + (lane >> 2);
        int r1 = r0 + 8;
#pragma unroll
        for (int nt = 0; nt < 4; nt++) {
            int c = wn + nt * 8 + (lane & 3) * 2;
            float bs0 = 0.f, bs1 = 0.f;
            if (mat == 0) { bs0 = __ldg(&b1[c]); bs1 = __ldg(&b1[c + 1]); }
            if (r0 < NN) {
                float2 v = make_float2(acc[mt][nt][0] + bs0, acc[mt][nt][1] + bs1);
                *reinterpret_cast<float2*>(outp + (size_t)r0 * F + c) = v;
            }
            if (r1 < NN) {
                float2 v = make_float2(acc[mt][nt][2] + bs0, acc[mt][nt][3] + bs1);
                *reinterpret_cast<float2*>(outp + (size_t)r1 * F + c) = v;
            }
        }
    }
}

// ---------------- layer-1 aggregate + combine + relu ----------------
__global__ void agg1_k() {
    int gwarp = (blockIdx.x * blockDim.x + threadIdx.x) >> 5;
    if (gwarp >= NN) return;
    int lane = threadIdx.x & 31;
    int beg = g_rowoff[gwarp], end = g_rowoff[gwarp + 1];
    float4 s = make_float4(0.f, 0.f, 0.f, 0.f);
    for (int e = beg; e < end; e++) {
        int sn = g_esrc[e];
        float4 v = reinterpret_cast<const float4*>(g_nb + (size_t)sn * F)[lane];
        s.x += v.x; s.y += v.y; s.z += v.z; s.w += v.w;
    }
    float inv = 1.0f / fmaxf((float)(end - beg), 1.0f);
    float4* hp = reinterpret_cast<float4*>(g_h1 + (size_t)gwarp * F);
    float4 a = hp[lane];
    a.x = fmaxf(a.x + s.x * inv, 0.f);
    a.y = fmaxf(a.y + s.y * inv, 0.f);
    a.z = fmaxf(a.z + s.z * inv, 0.f);
    a.w = fmaxf(a.w + s.w * inv, 0.f);
    hp[lane] = a;
}

// ---------------- layer-2 GEMM ----------------
__global__ void gemm2_k(const float* __restrict__ Ws, const float* __restrict__ Wn,
                        const float* __restrict__ b2, float* __restrict__ out)
{
    __shared__ float Xs[8][132];
    __shared__ float Wsh[128][32];
    int tid = threadIdx.x;
    for (int i = tid; i < 128 * 32; i += 256) {
        int k = i >> 5, c = i & 31;
        Wsh[k][c] = (c < 16) ? Ws[k * 16 + c] : Wn[k * 16 + (c - 16)];
    }
    int rowBase = blockIdx.x * 8;
    for (int i = tid; i < 8 * 128; i += 256) {
        int r = i >> 7, k = i & 127;
        int gr = rowBase + r;
        Xs[r][k] = (gr < NN) ? g_h1[(size_t)gr * 128 + k] : 0.f;
    }
    __syncthreads();
    int r = tid >> 5, c = tid & 31;
    float acc = 0.f;
#pragma unroll 16
    for (int k = 0; k < 128; k++) acc += Xs[r][k] * Wsh[k][c];
    int gr = rowBase + r;
    if (gr < NN) {
        if (c < 16) out[(size_t)gr * NC + c] = acc + b2[c];
        else        g_D[(size_t)gr * NC + (c - 16)] = acc;
    }
}

// ---------------- layer-2 aggregate + add ----------------
__global__ void agg2_k(float* __restrict__ out) {
    int idx = blockIdx.x * blockDim.x + threadIdx.x;
    int node = idx >> 4;
    if (node >= NN) return;
    int dim = idx & 15;
    int beg = g_rowoff[node], end = g_rowoff[node + 1];
    float s = 0.f;
    for (int e = beg; e < end; e++)
        s += g_D[(size_t)g_esrc[e] * NC + dim];
    float inv = 1.0f / fmaxf((float)(end - beg), 1.0f);
    out[(size_t)node * NC + dim] += s * inv;
}

// ---------------- launch ----------------
extern "C" void kernel_launch(void* const* d_in, const int* in_sizes, int n_in,
                              void* d_out, int out_size)
{
    const float* in_feat = (const float*)d_in[0];
    const void*  src     = d_in[1];
    const void*  dst     = d_in[2];
    const float* Wself1  = (const float*)d_in[3];
    const float* Wneigh1 = (const float*)d_in[4];
    const float* b1      = (const float*)d_in[5];
    const float* Wself2  = (const float*)d_in[6];
    const float* Wneigh2 = (const float*)d_in[7];
    const float* b2      = (const float*)d_in[8];
    float* out = (float*)d_out;

    static int smem_set = 0;
    if (!smem_set) {
        cudaFuncSetAttribute(gemm1_mma, cudaFuncAttributeMaxDynamicSharedMemorySize, SMEM_G1);
        smem_set = 1;
    }

    // dtype detection + CSR build
    detect_k<<<1, 32>>>((const int*)dst);
    zero_k <<<(NN + 255) / 256, 256>>>();
    count_k<<<(NE + 255) / 256, 256>>>(dst);
    scanA_k<<<NBLK, 256>>>();
    scanB_k<<<1, 256>>>();
    scanC_k<<<(NN + 255) / 256, 256>>>();
    fill_k <<<(NE + 255) / 256, 256>>>(src, dst);

    // bf16 hi/lo conversions
    convx_k<<<(NN * F / 4 + 255) / 256, 256>>>(in_feat);
    convw_k<<<(2 * F * F + 255) / 256, 256>>>(Wself1, Wneigh1);

    // layer 1: both projections via mma.sync tensor path
    dim3 g1(2, (NN + 127) / 128);
    gemm1_mma<<<g1, 512, SMEM_G1>>>(b1);

    // layer 1: aggregate + combine + relu (h1 in place)
    agg1_k<<<(NN * 32 + 255) / 256, 256>>>();

    // layer 2: projections
    gemm2_k<<<(NN + 7) / 8, 256>>>(Wself2, Wneigh2, b2, out);

    // layer 2: aggregate + add
    agg2_k<<<(NN * 16 + 255) / 256, 256>>>(out);
}

// round 6
// speedup vs baseline: 2.1371x; 1.8648x over previous
#include <cuda_runtime.h>
#include <cuda_bf16.h>
#include <cstdint>

#define NN 50000
#define NE 800000
#define F 128
#define NC 16
#define NBLK 196   // 196*256 = 50176 >= NN

// ---------------- scratch (static device globals; no allocs) ----------------
__device__ float g_h1[(size_t)NN * F];    // gemm1 self-proj + b1 (pre-relu)
__device__ float g_nb[(size_t)NN * F];    // gemm1 neigh-proj
__device__ float g_D [(size_t)NN * NC];   // h1@W_neigh2
__device__ int   g_deg[NN];
__device__ int   g_cur[NN];
__device__ int   g_rowoff[NN + 1];
__device__ int   g_esrc[NE];
__device__ int   g_part[NBLK * 256];
__device__ int   g_bsum[NBLK];
__device__ int   g_boff[NBLK];
__device__ int   g_is64;
// bf16 hi/lo split operands
__device__ __nv_bfloat16 g_wThi[2 * F * F];   // layer1 [mat][n][k] = W[k][n]
__device__ __nv_bfloat16 g_wTlo[2 * F * F];
__device__ __nv_bfloat16 g_w2Thi[32 * F];     // layer2 cat [n][k] (n<16 self, else neigh)
__device__ __nv_bfloat16 g_w2Tlo[32 * F];
__device__ __nv_bfloat16 g_h1hi[(size_t)NN * F];  // relu(h1) hi/lo
__device__ __nv_bfloat16 g_h1lo[(size_t)NN * F];

// ---------------- helpers ----------------
__device__ __forceinline__ uint32_t smem_u32(const void* p) {
    uint32_t a;
    asm("{ .reg .u64 t; cvta.to.shared.u64 t, %1; cvt.u32.u64 %0, t; }"
        : "=r"(a) : "l"(p));
    return a;
}
__device__ __forceinline__ void ldm_x4(uint32_t* r, uint32_t addr) {
    asm volatile("ldmatrix.sync.aligned.m8n8.x4.shared.b16 {%0,%1,%2,%3}, [%4];"
                 : "=r"(r[0]), "=r"(r[1]), "=r"(r[2]), "=r"(r[3]) : "r"(addr));
}
__device__ __forceinline__ void ldm_x2(uint32_t* r, uint32_t addr) {
    asm volatile("ldmatrix.sync.aligned.m8n8.x2.shared.b16 {%0,%1}, [%2];"
                 : "=r"(r[0]), "=r"(r[1]) : "r"(addr));
}
__device__ __forceinline__ void mma16816(float* d, const uint32_t* a, const uint32_t* b) {
    asm volatile("mma.sync.aligned.m16n8k16.row.col.f32.bf16.bf16.f32 "
                 "{%0,%1,%2,%3}, {%4,%5,%6,%7}, {%8,%9}, {%0,%1,%2,%3};"
                 : "+f"(d[0]), "+f"(d[1]), "+f"(d[2]), "+f"(d[3])
                 : "r"(a[0]), "r"(a[1]), "r"(a[2]), "r"(a[3]), "r"(b[0]), "r"(b[1]));
}
__device__ __forceinline__ uint32_t pack_bf2(float a, float b) {
    __nv_bfloat162 t(__float2bfloat16(a), __float2bfloat16(b));
    return *reinterpret_cast<uint32_t*>(&t);
}

// ---------------- zero + dtype detection ----------------
__global__ void zero_k(const int* __restrict__ dst32) {
    int i = blockIdx.x * blockDim.x + threadIdx.x;
    if (i < NN) { g_deg[i] = 0; g_cur[i] = 0; }
    if (blockIdx.x == 0 && threadIdx.x == 0) {
        int all_zero = 1;
        for (int j = 0; j < 256; j++)
            if (dst32[2 * j + 1] != 0) { all_zero = 0; break; }
        g_is64 = all_zero;
    }
}
__device__ __forceinline__ int load_idx(const void* p, int i) {
    if (g_is64) return (int)((const long long*)p)[i];
    return ((const int*)p)[i];
}

// ---------------- CSR build ----------------
__global__ void count_k(const void* __restrict__ dst) {
    int i = blockIdx.x * blockDim.x + threadIdx.x;
    if (i < NE) {
        int d = load_idx(dst, i);
        if (d >= 0 && d < NN) atomicAdd(&g_deg[d], 1);
    }
}
__global__ void scanA_k() {
    __shared__ int sh[256];
    int t = threadIdx.x, i = blockIdx.x * 256 + t;
    int v = (i < NN) ? g_deg[i] : 0;
    sh[t] = v;
    __syncthreads();
#pragma unroll
    for (int off = 1; off < 256; off <<= 1) {
        int u = (t >= off) ? sh[t - off] : 0;
        __syncthreads();
        sh[t] += u;
        __syncthreads();
    }
    g_part[i] = sh[t];
    if (t == 255) g_bsum[blockIdx.x] = sh[255];
}
__global__ void scanB_k() {
    __shared__ int sh[256];
    int t = threadIdx.x;
    int v = (t < NBLK) ? g_bsum[t] : 0;
    sh[t] = v;
    __syncthreads();
#pragma unroll
    for (int off = 1; off < 256; off <<= 1) {
        int u = (t >= off) ? sh[t - off] : 0;
        __syncthreads();
        sh[t] += u;
        __syncthreads();
    }
    if (t < NBLK) g_boff[t] = sh[t] - v;  // exclusive
}
__global__ void scanC_k() {
    int i = blockIdx.x * blockDim.x + threadIdx.x;
    if (i < NN) {
        g_rowoff[i + 1] = g_part[i] + g_boff[i >> 8];
        if (i == 0) g_rowoff[0] = 0;
    }
}
__global__ void fill_k(const void* __restrict__ src, const void* __restrict__ dst) {
    int i = blockIdx.x * blockDim.x + threadIdx.x;
    if (i < NE) {
        int d = load_idx(dst, i);
        int s = load_idx(src, i);
        if (d < 0 || d >= NN || s < 0 || s >= NN) return;
        int pos = atomicAdd(&g_cur[d], 1);
        int off = g_rowoff[d] + pos;
        if (off < NE) g_esrc[off] = s;
    }
}

// ---------------- weight conversions (both layers, one kernel) --------------
__global__ void convw_k(const float* __restrict__ Ws1, const float* __restrict__ Wn1,
                        const float* __restrict__ Ws2, const float* __restrict__ Wn2) {
    int i = blockIdx.x * blockDim.x + threadIdx.x;
    if (i < 2 * F * F) {                 // layer1: [mat][n][k] = W[k][n]
        int mat = i >> 14, n = (i >> 7) & 127, k = i & 127;
        float w = (mat == 0) ? Ws1[k * F + n] : Wn1[k * F + n];
        __nv_bfloat16 h = __float2bfloat16(w);
        g_wThi[i] = h;
        g_wTlo[i] = __float2bfloat16(w - __bfloat162float(h));
    } else if (i < 2 * F * F + 32 * F) { // layer2 cat: [n][k]
        int i2 = i - 2 * F * F;
        int n = i2 >> 7, k = i2 & 127;
        float w = (n < 16) ? Ws2[k * 16 + n] : Wn2[k * 16 + (n - 16)];
        __nv_bfloat16 h = __float2bfloat16(w);
        g_w2Thi[i2] = h;
        g_w2Tlo[i2] = __float2bfloat16(w - __bfloat162float(h));
    }
}

// ---------------- layer-1 GEMM (mma.sync, fused fp32->bf16 hi/lo) ----------
#define RS 136                       // smem row stride in bf16 (272 bytes)
#define TILE_B (128 * RS * 2)        // 34816 bytes
#define OFF_AHI 0
#define OFF_ALO (TILE_B)
#define OFF_BHI (2 * TILE_B)
#define OFF_BLO (3 * TILE_B)
#define SMEM_G1 (4 * TILE_B)

__global__ void __launch_bounds__(512, 1)
gemm1_mma(const float* __restrict__ X, const float* __restrict__ b1) {
    extern __shared__ char smem[];
    uint32_t sb = smem_u32(smem);
    int tid = threadIdx.x, wid = tid >> 5, lane = tid & 31;
    int rowBase = blockIdx.y * 128;
    int mat = blockIdx.x;
    const __nv_bfloat16* wthi = g_wThi + (size_t)mat * F * F;
    const __nv_bfloat16* wtlo = g_wTlo + (size_t)mat * F * F;

    // stage: A from fp32 X with in-flight hi/lo split; B from pre-split W^T
    for (int i = tid; i < 128 * 16; i += 512) {
        int r = i >> 4, cc = i & 15;
        uint32_t so = (uint32_t)r * (RS * 2) + cc * 16;
        int gr = rowBase + r;
        float v[8] = {0.f, 0.f, 0.f, 0.f, 0.f, 0.f, 0.f, 0.f};
        if (gr < NN) {
            const float4* xp = reinterpret_cast<const float4*>(X + (size_t)gr * F + cc * 8);
            float4 f0 = xp[0], f1 = xp[1];
            v[0] = f0.x; v[1] = f0.y; v[2] = f0.z; v[3] = f0.w;
            v[4] = f1.x; v[5] = f1.y; v[6] = f1.z; v[7] = f1.w;
        }
        uint4 uh, ul;
        {
            float hf[8], lf[8];
#pragma unroll
            for (int j = 0; j < 8; j++) {
                __nv_bfloat16 h = __float2bfloat16(v[j]);
                hf[j] = __bfloat162float(h);
                lf[j] = v[j] - hf[j];
            }
            uh.x = pack_bf2(hf[0], hf[1]); uh.y = pack_bf2(hf[2], hf[3]);
            uh.z = pack_bf2(hf[4], hf[5]); uh.w = pack_bf2(hf[6], hf[7]);
            ul.x = pack_bf2(lf[0], lf[1]); ul.y = pack_bf2(lf[2], lf[3]);
            ul.z = pack_bf2(lf[4], lf[5]); ul.w = pack_bf2(lf[6], lf[7]);
        }
        *reinterpret_cast<uint4*>(smem + OFF_AHI + so) = uh;
        *reinterpret_cast<uint4*>(smem + OFF_ALO + so) = ul;
        *reinterpret_cast<uint4*>(smem + OFF_BHI + so) =
            reinterpret_cast<const uint4*>(wthi + (size_t)r * F)[cc];
        *reinterpret_cast<uint4*>(smem + OFF_BLO + so) =
            reinterpret_cast<const uint4*>(wtlo + (size_t)r * F)[cc];
    }
    __syncthreads();

    int wm = (wid & 3) * 32, wn = (wid >> 2) * 32;
    float acc[2][4][4];
#pragma unroll
    for (int mt = 0; mt < 2; mt++)
#pragma unroll
        for (int nt = 0; nt < 4; nt++)
#pragma unroll
            for (int e = 0; e < 4; e++) acc[mt][nt][e] = 0.f;

    uint32_t a_row = wm + (lane & 15);
    uint32_t a_coff = (lane >> 4) * 16;
    uint32_t b_row = wn + (lane & 7);
    uint32_t b_coff = ((lane >> 3) & 1) * 16;

#pragma unroll
    for (int ks = 0; ks < 8; ks++) {
        uint32_t kb = ks * 32;
        uint32_t ahi[2][4], alo[2][4], bhi[4][2], blo[4][2];
#pragma unroll
        for (int mt = 0; mt < 2; mt++) {
            uint32_t ro = (a_row + mt * 16) * (RS * 2) + kb + a_coff;
            ldm_x4(ahi[mt], sb + OFF_AHI + ro);
            ldm_x4(alo[mt], sb + OFF_ALO + ro);
        }
#pragma unroll
        for (int nt = 0; nt < 4; nt++) {
            uint32_t ro = (b_row + nt * 8) * (RS * 2) + kb + b_coff;
            ldm_x2(bhi[nt], sb + OFF_BHI + ro);
            ldm_x2(blo[nt], sb + OFF_BLO + ro);
        }
#pragma unroll
        for (int mt = 0; mt < 2; mt++)
#pragma unroll
            for (int nt = 0; nt < 4; nt++) {
                mma16816(acc[mt][nt], ahi[mt], bhi[nt]);
                mma16816(acc[mt][nt], alo[mt], bhi[nt]);
                mma16816(acc[mt][nt], ahi[mt], blo[nt]);
            }
    }

    float* outp = (mat == 0) ? g_h1 : g_nb;
#pragma unroll
    for (int mt = 0; mt < 2; mt++) {
        int r0 = rowBase + wm + mt * 16 + (lane >> 2);
        int r1 = r0 + 8;
#pragma unroll
        for (int nt = 0; nt < 4; nt++) {
            int c = wn + nt * 8 + (lane & 3) * 2;
            float bs0 = 0.f, bs1 = 0.f;
            if (mat == 0) { bs0 = __ldg(&b1[c]); bs1 = __ldg(&b1[c + 1]); }
            if (r0 < NN)
                *reinterpret_cast<float2*>(outp + (size_t)r0 * F + c) =
                    make_float2(acc[mt][nt][0] + bs0, acc[mt][nt][1] + bs1);
            if (r1 < NN)
                *reinterpret_cast<float2*>(outp + (size_t)r1 * F + c) =
                    make_float2(acc[mt][nt][2] + bs0, acc[mt][nt][3] + bs1);
        }
    }
}

// ------- layer-1 aggregate + combine + relu -> bf16 hi/lo (for gemm2) -------
__global__ void agg1_k() {
    int node = (blockIdx.x * blockDim.x + threadIdx.x) >> 5;
    if (node >= NN) return;
    int lane = threadIdx.x & 31;
    int beg = g_rowoff[node], end = g_rowoff[node + 1];
    float4 s = make_float4(0.f, 0.f, 0.f, 0.f);
    int e = beg;
    for (; e + 4 <= end; e += 4) {
        int i0 = g_esrc[e], i1 = g_esrc[e + 1], i2 = g_esrc[e + 2], i3 = g_esrc[e + 3];
        float4 v0 = reinterpret_cast<const float4*>(g_nb + (size_t)i0 * F)[lane];
        float4 v1 = reinterpret_cast<const float4*>(g_nb + (size_t)i1 * F)[lane];
        float4 v2 = reinterpret_cast<const float4*>(g_nb + (size_t)i2 * F)[lane];
        float4 v3 = reinterpret_cast<const float4*>(g_nb + (size_t)i3 * F)[lane];
        s.x += v0.x + v1.x + v2.x + v3.x;
        s.y += v0.y + v1.y + v2.y + v3.y;
        s.z += v0.z + v1.z + v2.z + v3.z;
        s.w += v0.w + v1.w + v2.w + v3.w;
    }
    for (; e < end; e++) {
        float4 v = reinterpret_cast<const float4*>(g_nb + (size_t)g_esrc[e] * F)[lane];
        s.x += v.x; s.y += v.y; s.z += v.z; s.w += v.w;
    }
    float inv = 1.0f / fmaxf((float)(end - beg), 1.0f);
    float4 a = reinterpret_cast<const float4*>(g_h1 + (size_t)node * F)[lane];
    float r0 = fmaxf(a.x + s.x * inv, 0.f);
    float r1 = fmaxf(a.y + s.y * inv, 0.f);
    float r2 = fmaxf(a.z + s.z * inv, 0.f);
    float r3 = fmaxf(a.w + s.w * inv, 0.f);
    // hi/lo bf16 split, 4 values -> uint2 each
    float h0 = __bfloat162float(__float2bfloat16(r0));
    float h1 = __bfloat162float(__float2bfloat16(r1));
    float h2 = __bfloat162float(__float2bfloat16(r2));
    float h3 = __bfloat162float(__float2bfloat16(r3));
    uint2 uh = make_uint2(pack_bf2(h0, h1), pack_bf2(h2, h3));
    uint2 ul = make_uint2(pack_bf2(r0 - h0, r1 - h1), pack_bf2(r2 - h2, r3 - h3));
    reinterpret_cast<uint2*>(g_h1hi + (size_t)node * F)[lane] = uh;
    reinterpret_cast<uint2*>(g_h1lo + (size_t)node * F)[lane] = ul;
}

// ---------------- layer-2 GEMM (mma.sync, N=32 = [self|neigh]) --------------
#define B2_B (32 * RS * 2)           // 8704 bytes
#define OFF2_AHI 0
#define OFF2_ALO (TILE_B)
#define OFF2_BHI (2 * TILE_B)
#define OFF2_BLO (2 * TILE_B + B2_B)
#define SMEM_G2 (2 * TILE_B + 2 * B2_B)

__global__ void __launch_bounds__(256, 1)
gemm2_mma(const float* __restrict__ b2, float* __restrict__ out) {
    extern __shared__ char smem[];
    uint32_t sb = smem_u32(smem);
    int tid = threadIdx.x, wid = tid >> 5, lane = tid & 31;
    int rowBase = blockIdx.x * 128;

    for (int i = tid; i < 128 * 16; i += 256) {
        int r = i >> 4, cc = i & 15;
        uint32_t so = (uint32_t)r * (RS * 2) + cc * 16;
        int gr = rowBase + r;
        uint4 vh = make_uint4(0, 0, 0, 0), vl = make_uint4(0, 0, 0, 0);
        if (gr < NN) {
            vh = reinterpret_cast<const uint4*>(g_h1hi + (size_t)gr * F)[cc];
            vl = reinterpret_cast<const uint4*>(g_h1lo + (size_t)gr * F)[cc];
        }
        *reinterpret_cast<uint4*>(smem + OFF2_AHI + so) = vh;
        *reinterpret_cast<uint4*>(smem + OFF2_ALO + so) = vl;
    }
    for (int i = tid; i < 32 * 16; i += 256) {
        int r = i >> 4, cc = i & 15;
        uint32_t so = (uint32_t)r * (RS * 2) + cc * 16;
        *reinterpret_cast<uint4*>(smem + OFF2_BHI + so) =
            reinterpret_cast<const uint4*>(g_w2Thi + (size_t)r * F)[cc];
        *reinterpret_cast<uint4*>(smem + OFF2_BLO + so) =
            reinterpret_cast<const uint4*>(g_w2Tlo + (size_t)r * F)[cc];
    }
    __syncthreads();

    int wm = (wid & 3) * 32, wn = (wid >> 2) * 16;
    float acc[2][2][4];
#pragma unroll
    for (int mt = 0; mt < 2; mt++)
#pragma unroll
        for (int nt = 0; nt < 2; nt++)
#pragma unroll
            for (int e = 0; e < 4; e++) acc[mt][nt][e] = 0.f;

    uint32_t a_row = wm + (lane & 15);
    uint32_t a_coff = (lane >> 4) * 16;
    uint32_t b_row = wn + (lane & 7);
    uint32_t b_coff = ((lane >> 3) & 1) * 16;

#pragma unroll
    for (int ks = 0; ks < 8; ks++) {
        uint32_t kb = ks * 32;
        uint32_t ahi[2][4], alo[2][4], bhi[2][2], blo[2][2];
#pragma unroll
        for (int mt = 0; mt < 2; mt++) {
            uint32_t ro = (a_row + mt * 16) * (RS * 2) + kb + a_coff;
            ldm_x4(ahi[mt], sb + OFF2_AHI + ro);
            ldm_x4(alo[mt], sb + OFF2_ALO + ro);
        }
#pragma unroll
        for (int nt = 0; nt < 2; nt++) {
            uint32_t ro = (b_row + nt * 8) * (RS * 2) + kb + b_coff;
            ldm_x2(bhi[nt], sb + OFF2_BHI + ro);
            ldm_x2(blo[nt], sb + OFF2_BLO + ro);
        }
#pragma unroll
        for (int mt = 0; mt < 2; mt++)
#pragma unroll
            for (int nt = 0; nt < 2; nt++) {
                mma16816(acc[mt][nt], ahi[mt], bhi[nt]);
                mma16816(acc[mt][nt], alo[mt], bhi[nt]);
                mma16816(acc[mt][nt], ahi[mt], blo[nt]);
            }
    }

#pragma unroll
    for (int mt = 0; mt < 2; mt++) {
        int r0 = rowBase + wm + mt * 16 + (lane >> 2);
        int r1 = r0 + 8;
#pragma unroll
        for (int nt = 0; nt < 2; nt++) {
            int cg = wn + nt * 8 + (lane & 3) * 2;  // 0..31
            if (cg < 16) {
                float bs0 = __ldg(&b2[cg]), bs1 = __ldg(&b2[cg + 1]);
                if (r0 < NN)
                    *reinterpret_cast<float2*>(out + (size_t)r0 * NC + cg) =
                        make_float2(acc[mt][nt][0] + bs0, acc[mt][nt][1] + bs1);
                if (r1 < NN)
                    *reinterpret_cast<float2*>(out + (size_t)r1 * NC + cg) =
                        make_float2(acc[mt][nt][2] + bs0, acc[mt][nt][3] + bs1);
            } else {
                int cd = cg - 16;
                if (r0 < NN)
                    *reinterpret_cast<float2*>(g_D + (size_t)r0 * NC + cd) =
                        make_float2(acc[mt][nt][0], acc[mt][nt][1]);
                if (r1 < NN)
                    *reinterpret_cast<float2*>(g_D + (size_t)r1 * NC + cd) =
                        make_float2(acc[mt][nt][2], acc[mt][nt][3]);
            }
        }
    }
}

// ---------------- layer-2 aggregate + add ----------------
__global__ void agg2_k(float* __restrict__ out) {
    int idx = blockIdx.x * blockDim.x + threadIdx.x;
    int node = idx >> 4;
    if (node >= NN) return;
    int dim = idx & 15;
    int beg = g_rowoff[node], end = g_rowoff[node + 1];
    float s = 0.f;
    int e = beg;
    for (; e + 4 <= end; e += 4) {
        int i0 = g_esrc[e], i1 = g_esrc[e + 1], i2 = g_esrc[e + 2], i3 = g_esrc[e + 3];
        float v0 = g_D[(size_t)i0 * NC + dim];
        float v1 = g_D[(size_t)i1 * NC + dim];
        float v2 = g_D[(size_t)i2 * NC + dim];
        float v3 = g_D[(size_t)i3 * NC + dim];
        s += (v0 + v1) + (v2 + v3);
    }
    for (; e < end; e++)
        s += g_D[(size_t)g_esrc[e] * NC + dim];
    float inv = 1.0f / fmaxf((float)(end - beg), 1.0f);
    out[(size_t)node * NC + dim] += s * inv;
}

// ---------------- launch ----------------
extern "C" void kernel_launch(void* const* d_in, const int* in_sizes, int n_in,
                              void* d_out, int out_size)
{
    const float* in_feat = (const float*)d_in[0];
    const void*  src     = d_in[1];
    const void*  dst     = d_in[2];
    const float* Wself1  = (const float*)d_in[3];
    const float* Wneigh1 = (const float*)d_in[4];
    const float* b1      = (const float*)d_in[5];
    const float* Wself2  = (const float*)d_in[6];
    const float* Wneigh2 = (const float*)d_in[7];
    const float* b2      = (const float*)d_in[8];
    float* out = (float*)d_out;

    static int smem_set = 0;
    if (!smem_set) {
        cudaFuncSetAttribute(gemm1_mma, cudaFuncAttributeMaxDynamicSharedMemorySize, SMEM_G1);
        cudaFuncSetAttribute(gemm2_mma, cudaFuncAttributeMaxDynamicSharedMemorySize, SMEM_G2);
        smem_set = 1;
    }

    // CSR build (+ dtype detection inside zero_k)
    zero_k <<<(NN + 255) / 256, 256>>>((const int*)dst);
    count_k<<<(NE + 255) / 256, 256>>>(dst);
    scanA_k<<<NBLK, 256>>>();
    scanB_k<<<1, 256>>>();
    scanC_k<<<(NN + 255) / 256, 256>>>();
    fill_k <<<(NE + 255) / 256, 256>>>(src, dst);

    // weight conversions (both layers)
    convw_k<<<(2 * F * F + 32 * F + 255) / 256, 256>>>(Wself1, Wneigh1, Wself2, Wneigh2);

    // layer 1: both projections (X converted in-kernel)
    dim3 g1(2, (NN + 127) / 128);
    gemm1_mma<<<g1, 512, SMEM_G1>>>(in_feat, b1);

    // layer 1: aggregate + combine + relu -> bf16 hi/lo
    agg1_k<<<(NN * 32 + 255) / 256, 256>>>();

    // layer 2: projections (out self part + bias; g_D neigh part)
    gemm2_mma<<<(NN + 127) / 128, 256, SMEM_G2>>>(b2, out);

    // layer 2: aggregate + add
    agg2_k<<<(NN * 16 + 255) / 256, 256>>>(out);
}

// round 7
// speedup vs baseline: 2.2332x; 1.0450x over previous
#include <cuda_runtime.h>
#include <cuda_bf16.h>
#include <cstdint>

#define NN 50000
#define NE 800000
#define F 128
#define NC 16
#define NBLK 196   // 196*256 = 50176 >= NN

// ---------------- scratch (static device globals; no allocs) ----------------
__device__ float g_h1[(size_t)NN * F];    // gemm1 self-proj + b1 (pre-relu)
__device__ float g_nb[(size_t)NN * F];    // gemm1 neigh-proj
__device__ float g_D [(size_t)NN * NC];   // h1@W_neigh2
__device__ int   g_deg[NN];
__device__ int   g_cur[NN];
__device__ int   g_rowoff[NN + 1];
__device__ int   g_esrc[NE];
__device__ int   g_part[NBLK * 256];
__device__ int   g_bsum[NBLK];
__device__ int   g_is64;
// bf16 hi/lo split operands
__device__ __nv_bfloat16 g_wThi[2 * F * F];   // layer1 [mat][n][k] = W[k][n]
__device__ __nv_bfloat16 g_wTlo[2 * F * F];
__device__ __nv_bfloat16 g_w2Thi[32 * F];     // layer2 cat [n][k] (n<16 self, else neigh)
__device__ __nv_bfloat16 g_w2Tlo[32 * F];
__device__ __nv_bfloat16 g_h1hi[(size_t)NN * F];  // relu(h1) hi/lo
__device__ __nv_bfloat16 g_h1lo[(size_t)NN * F];

// ---------------- helpers ----------------
__device__ __forceinline__ uint32_t smem_u32(const void* p) {
    uint32_t a;
    asm("{ .reg .u64 t; cvta.to.shared.u64 t, %1; cvt.u32.u64 %0, t; }"
        : "=r"(a) : "l"(p));
    return a;
}
__device__ __forceinline__ void ldm_x4(uint32_t* r, uint32_t addr) {
    asm volatile("ldmatrix.sync.aligned.m8n8.x4.shared.b16 {%0,%1,%2,%3}, [%4];"
                 : "=r"(r[0]), "=r"(r[1]), "=r"(r[2]), "=r"(r[3]) : "r"(addr));
}
__device__ __forceinline__ void ldm_x2(uint32_t* r, uint32_t addr) {
    asm volatile("ldmatrix.sync.aligned.m8n8.x2.shared.b16 {%0,%1}, [%2];"
                 : "=r"(r[0]), "=r"(r[1]) : "r"(addr));
}
__device__ __forceinline__ void mma16816(float* d, const uint32_t* a, const uint32_t* b) {
    asm volatile("mma.sync.aligned.m16n8k16.row.col.f32.bf16.bf16.f32 "
                 "{%0,%1,%2,%3}, {%4,%5,%6,%7}, {%8,%9}, {%0,%1,%2,%3};"
                 : "+f"(d[0]), "+f"(d[1]), "+f"(d[2]), "+f"(d[3])
                 : "r"(a[0]), "r"(a[1]), "r"(a[2]), "r"(a[3]), "r"(b[0]), "r"(b[1]));
}
__device__ __forceinline__ uint32_t pack_bf2(float a, float b) {
    __nv_bfloat162 t(__float2bfloat16(a), __float2bfloat16(b));
    return *reinterpret_cast<uint32_t*>(&t);
}

// -------- prep: zero deg/cur + dtype detect + weight conversions ------------
__global__ void prep_k(const int* __restrict__ dst32,
                       const float* __restrict__ Ws1, const float* __restrict__ Wn1,
                       const float* __restrict__ Ws2, const float* __restrict__ Wn2) {
    int i = blockIdx.x * blockDim.x + threadIdx.x;
    if (i < NN) { g_deg[i] = 0; g_cur[i] = 0; }
    if (i == 0) {
        int all_zero = 1;
        for (int j = 0; j < 256; j++)
            if (dst32[2 * j + 1] != 0) { all_zero = 0; break; }
        g_is64 = all_zero;
    }
    if (i < 2 * F * F) {                 // layer1: [mat][n][k] = W[k][n]
        int mat = i >> 14, n = (i >> 7) & 127, k = i & 127;
        float w = (mat == 0) ? Ws1[k * F + n] : Wn1[k * F + n];
        __nv_bfloat16 h = __float2bfloat16(w);
        g_wThi[i] = h;
        g_wTlo[i] = __float2bfloat16(w - __bfloat162float(h));
    } else if (i < 2 * F * F + 32 * F) { // layer2 cat: [n][k]
        int i2 = i - 2 * F * F;
        int n = i2 >> 7, k = i2 & 127;
        float w = (n < 16) ? Ws2[k * 16 + n] : Wn2[k * 16 + (n - 16)];
        __nv_bfloat16 h = __float2bfloat16(w);
        g_w2Thi[i2] = h;
        g_w2Tlo[i2] = __float2bfloat16(w - __bfloat162float(h));
    }
}
__device__ __forceinline__ int load_idx(const void* p, int i) {
    if (g_is64) return (int)((const long long*)p)[i];
    return ((const int*)p)[i];
}

// ---------------- CSR build ----------------
__global__ void count_k(const void* __restrict__ dst) {
    int i = blockIdx.x * blockDim.x + threadIdx.x;
    if (i < NE) {
        int d = load_idx(dst, i);
        if (d >= 0 && d < NN) atomicAdd(&g_deg[d], 1);
    }
}
__global__ void scanA_k() {
    __shared__ int sh[256];
    int t = threadIdx.x, i = blockIdx.x * 256 + t;
    int v = (i < NN) ? g_deg[i] : 0;
    sh[t] = v;
    __syncthreads();
#pragma unroll
    for (int off = 1; off < 256; off <<= 1) {
        int u = (t >= off) ? sh[t - off] : 0;
        __syncthreads();
        sh[t] += u;
        __syncthreads();
    }
    g_part[i] = sh[t];
    if (t == 255) g_bsum[blockIdx.x] = sh[255];
}
// rowoff[i+1] = part[i] + sum(bsum[0..blk-1]); blk == i>>8 == blockIdx.x
__global__ void scanC_k() {
    __shared__ int red[256];
    int t = threadIdx.x, b = blockIdx.x;
    red[t] = (t < b) ? g_bsum[t] : 0;   // t < 256, bsum index < NBLK guaranteed by t < b <= 195
    __syncthreads();
#pragma unroll
    for (int off = 128; off >= 1; off >>= 1) {
        if (t < off) red[t] += red[t + off];
        __syncthreads();
    }
    int prefix = red[0];
    int i = b * 256 + t;
    if (i < NN) {
        g_rowoff[i + 1] = g_part[i] + prefix;
        if (i == 0) g_rowoff[0] = 0;
    }
}
__global__ void fill_k(const void* __restrict__ src, const void* __restrict__ dst) {
    int i = blockIdx.x * blockDim.x + threadIdx.x;
    if (i < NE) {
        int d = load_idx(dst, i);
        int s = load_idx(src, i);
        if (d < 0 || d >= NN || s < 0 || s >= NN) return;
        int pos = atomicAdd(&g_cur[d], 1);
        int off = g_rowoff[d] + pos;
        if (off < NE) g_esrc[off] = s;
    }
}

// ------- layer-1 GEMM: one CTA does BOTH projections (N = 256) --------------
#define RS 136                       // smem row stride in bf16 (272 bytes)
#define TILE_B (128 * RS * 2)        // 34816 bytes
#define OFF_AHI 0
#define OFF_ALO (TILE_B)
#define OFF_BHI (2 * TILE_B)         // 256 rows (mat0 then mat1)
#define OFF_BLO (4 * TILE_B)
#define SMEM_G1 (6 * TILE_B)         // 208896 B

__global__ void __launch_bounds__(512, 1)
gemm1_mma(const float* __restrict__ X, const float* __restrict__ b1) {
    extern __shared__ char smem[];
    uint32_t sb = smem_u32(smem);
    int tid = threadIdx.x, wid = tid >> 5, lane = tid & 31;
    int rowBase = blockIdx.x * 128;

    // stage A (fp32 -> bf16 hi/lo in flight)
    for (int i = tid; i < 128 * 16; i += 512) {
        int r = i >> 4, cc = i & 15;
        uint32_t so = (uint32_t)r * (RS * 2) + cc * 16;
        int gr = rowBase + r;
        float v[8] = {0.f, 0.f, 0.f, 0.f, 0.f, 0.f, 0.f, 0.f};
        if (gr < NN) {
            const float4* xp = reinterpret_cast<const float4*>(X + (size_t)gr * F + cc * 8);
            float4 f0 = xp[0], f1 = xp[1];
            v[0] = f0.x; v[1] = f0.y; v[2] = f0.z; v[3] = f0.w;
            v[4] = f1.x; v[5] = f1.y; v[6] = f1.z; v[7] = f1.w;
        }
        float hf[8], lf[8];
#pragma unroll
        for (int j = 0; j < 8; j++) {
            __nv_bfloat16 h = __float2bfloat16(v[j]);
            hf[j] = __bfloat162float(h);
            lf[j] = v[j] - hf[j];
        }
        uint4 uh = make_uint4(pack_bf2(hf[0], hf[1]), pack_bf2(hf[2], hf[3]),
                              pack_bf2(hf[4], hf[5]), pack_bf2(hf[6], hf[7]));
        uint4 ul = make_uint4(pack_bf2(lf[0], lf[1]), pack_bf2(lf[2], lf[3]),
                              pack_bf2(lf[4], lf[5]), pack_bf2(lf[6], lf[7]));
        *reinterpret_cast<uint4*>(smem + OFF_AHI + so) = uh;
        *reinterpret_cast<uint4*>(smem + OFF_ALO + so) = ul;
    }
    // stage B: 256 rows of W^T (mat0 rows 0-127, mat1 rows 128-255)
    for (int i = tid; i < 256 * 16; i += 512) {
        int r = i >> 4, cc = i & 15;
        uint32_t so = (uint32_t)r * (RS * 2) + cc * 16;
        *reinterpret_cast<uint4*>(smem + OFF_BHI + so) =
            reinterpret_cast<const uint4*>(g_wThi + (size_t)r * F)[cc];
        *reinterpret_cast<uint4*>(smem + OFF_BLO + so) =
            reinterpret_cast<const uint4*>(g_wTlo + (size_t)r * F)[cc];
    }
    __syncthreads();

    int wm = (wid & 3) * 32;       // warp rows
    int wn = (wid >> 2) * 64;      // warp cols (of 256)
    float acc[2][8][4];
#pragma unroll
    for (int mt = 0; mt < 2; mt++)
#pragma unroll
        for (int nt = 0; nt < 8; nt++)
#pragma unroll
            for (int e = 0; e < 4; e++) acc[mt][nt][e] = 0.f;

    uint32_t a_row = wm + (lane & 15);
    uint32_t a_coff = (lane >> 4) * 16;
    uint32_t b_row = wn + (lane & 7);
    uint32_t b_coff = ((lane >> 3) & 1) * 16;

#pragma unroll
    for (int ks = 0; ks < 8; ks++) {
        uint32_t kb = ks * 32;
        uint32_t ahi[2][4], alo[2][4];
#pragma unroll
        for (int mt = 0; mt < 2; mt++) {
            uint32_t ro = (a_row + mt * 16) * (RS * 2) + kb + a_coff;
            ldm_x4(ahi[mt], sb + OFF_AHI + ro);
            ldm_x4(alo[mt], sb + OFF_ALO + ro);
        }
#pragma unroll
        for (int half = 0; half < 2; half++) {
            uint32_t bhi[4][2], blo[4][2];
#pragma unroll
            for (int q = 0; q < 4; q++) {
                int nt = half * 4 + q;
                uint32_t ro = (b_row + nt * 8) * (RS * 2) + kb + b_coff;
                ldm_x2(bhi[q], sb + OFF_BHI + ro);
                ldm_x2(blo[q], sb + OFF_BLO + ro);
            }
#pragma unroll
            for (int mt = 0; mt < 2; mt++)
#pragma unroll
                for (int q = 0; q < 4; q++) {
                    int nt = half * 4 + q;
                    mma16816(acc[mt][nt], ahi[mt], bhi[q]);
                    mma16816(acc[mt][nt], alo[mt], bhi[q]);
                    mma16816(acc[mt][nt], ahi[mt], blo[q]);
                }
        }
    }

#pragma unroll
    for (int mt = 0; mt < 2; mt++) {
        int r0 = rowBase + wm + mt * 16 + (lane >> 2);
        int r1 = r0 + 8;
#pragma unroll
        for (int nt = 0; nt < 8; nt++) {
            int c = wn + nt * 8 + (lane & 3) * 2;   // 0..255
            float* outp;
            float bs0 = 0.f, bs1 = 0.f;
            int cc;
            if (c < 128) {
                outp = g_h1; cc = c;
                bs0 = __ldg(&b1[cc]); bs1 = __ldg(&b1[cc + 1]);
            } else {
                outp = g_nb; cc = c - 128;
            }
            if (r0 < NN)
                *reinterpret_cast<float2*>(outp + (size_t)r0 * F + cc) =
                    make_float2(acc[mt][nt][0] + bs0, acc[mt][nt][1] + bs1);
            if (r1 < NN)
                *reinterpret_cast<float2*>(outp + (size_t)r1 * F + cc) =
                    make_float2(acc[mt][nt][2] + bs0, acc[mt][nt][3] + bs1);
        }
    }
}

// ------- layer-1 aggregate + combine + relu -> bf16 hi/lo (for gemm2) -------
__global__ void agg1_k() {
    int node = (blockIdx.x * blockDim.x + threadIdx.x) >> 5;
    if (node >= NN) return;
    int lane = threadIdx.x & 31;
    int beg = g_rowoff[node], end = g_rowoff[node + 1];
    float4 s = make_float4(0.f, 0.f, 0.f, 0.f);
    int e = beg;
    for (; e + 4 <= end; e += 4) {
        int i0 = g_esrc[e], i1 = g_esrc[e + 1], i2 = g_esrc[e + 2], i3 = g_esrc[e + 3];
        float4 v0 = reinterpret_cast<const float4*>(g_nb + (size_t)i0 * F)[lane];
        float4 v1 = reinterpret_cast<const float4*>(g_nb + (size_t)i1 * F)[lane];
        float4 v2 = reinterpret_cast<const float4*>(g_nb + (size_t)i2 * F)[lane];
        float4 v3 = reinterpret_cast<const float4*>(g_nb + (size_t)i3 * F)[lane];
        s.x += v0.x + v1.x + v2.x + v3.x;
        s.y += v0.y + v1.y + v2.y + v3.y;
        s.z += v0.z + v1.z + v2.z + v3.z;
        s.w += v0.w + v1.w + v2.w + v3.w;
    }
    for (; e < end; e++) {
        float4 v = reinterpret_cast<const float4*>(g_nb + (size_t)g_esrc[e] * F)[lane];
        s.x += v.x; s.y += v.y; s.z += v.z; s.w += v.w;
    }
    float inv = 1.0f / fmaxf((float)(end - beg), 1.0f);
    float4 a = reinterpret_cast<const float4*>(g_h1 + (size_t)node * F)[lane];
    float r0 = fmaxf(a.x + s.x * inv, 0.f);
    float r1 = fmaxf(a.y + s.y * inv, 0.f);
    float r2 = fmaxf(a.z + s.z * inv, 0.f);
    float r3 = fmaxf(a.w + s.w * inv, 0.f);
    float h0 = __bfloat162float(__float2bfloat16(r0));
    float h1 = __bfloat162float(__float2bfloat16(r1));
    float h2 = __bfloat162float(__float2bfloat16(r2));
    float h3 = __bfloat162float(__float2bfloat16(r3));
    uint2 uh = make_uint2(pack_bf2(h0, h1), pack_bf2(h2, h3));
    uint2 ul = make_uint2(pack_bf2(r0 - h0, r1 - h1), pack_bf2(r2 - h2, r3 - h3));
    reinterpret_cast<uint2*>(g_h1hi + (size_t)node * F)[lane] = uh;
    reinterpret_cast<uint2*>(g_h1lo + (size_t)node * F)[lane] = ul;
}

// ---------------- layer-2 GEMM (mma.sync, N=32 = [self|neigh]) --------------
#define B2_B (32 * RS * 2)
#define OFF2_AHI 0
#define OFF2_ALO (TILE_B)
#define OFF2_BHI (2 * TILE_B)
#define OFF2_BLO (2 * TILE_B + B2_B)
#define SMEM_G2 (2 * TILE_B + 2 * B2_B)

__global__ void __launch_bounds__(256, 1)
gemm2_mma(const float* __restrict__ b2, float* __restrict__ out) {
    extern __shared__ char smem[];
    uint32_t sb = smem_u32(smem);
    int tid = threadIdx.x, wid = tid >> 5, lane = tid & 31;
    int rowBase = blockIdx.x * 128;

    for (int i = tid; i < 128 * 16; i += 256) {
        int r = i >> 4, cc = i & 15;
        uint32_t so = (uint32_t)r * (RS * 2) + cc * 16;
        int gr = rowBase + r;
        uint4 vh = make_uint4(0, 0, 0, 0), vl = make_uint4(0, 0, 0, 0);
        if (gr < NN) {
            vh = reinterpret_cast<const uint4*>(g_h1hi + (size_t)gr * F)[cc];
            vl = reinterpret_cast<const uint4*>(g_h1lo + (size_t)gr * F)[cc];
        }
        *reinterpret_cast<uint4*>(smem + OFF2_AHI + so) = vh;
        *reinterpret_cast<uint4*>(smem + OFF2_ALO + so) = vl;
    }
    for (int i = tid; i < 32 * 16; i += 256) {
        int r = i >> 4, cc = i & 15;
        uint32_t so = (uint32_t)r * (RS * 2) + cc * 16;
        *reinterpret_cast<uint4*>(smem + OFF2_BHI + so) =
            reinterpret_cast<const uint4*>(g_w2Thi + (size_t)r * F)[cc];
        *reinterpret_cast<uint4*>(smem + OFF2_BLO + so) =
            reinterpret_cast<const uint4*>(g_w2Tlo + (size_t)r * F)[cc];
    }
    __syncthreads();

    int wm = (wid & 3) * 32, wn = (wid >> 2) * 16;
    float acc[2][2][4];
#pragma unroll
    for (int mt = 0; mt < 2; mt++)
#pragma unroll
        for (int nt = 0; nt < 2; nt++)
#pragma unroll
            for (int e = 0; e < 4; e++) acc[mt][nt][e] = 0.f;

    uint32_t a_row = wm + (lane & 15);
    uint32_t a_coff = (lane >> 4) * 16;
    uint32_t b_row = wn + (lane & 7);
    uint32_t b_coff = ((lane >> 3) & 1) * 16;

#pragma unroll
    for (int ks = 0; ks < 8; ks++) {
        uint32_t kb = ks * 32;
        uint32_t ahi[2][4], alo[2][4], bhi[2][2], blo[2][2];
#pragma unroll
        for (int mt = 0; mt < 2; mt++) {
            uint32_t ro = (a_row + mt * 16) * (RS * 2) + kb + a_coff;
            ldm_x4(ahi[mt], sb + OFF2_AHI + ro);
            ldm_x4(alo[mt], sb + OFF2_ALO + ro);
        }
#pragma unroll
        for (int nt = 0; nt < 2; nt++) {
            uint32_t ro = (b_row + nt * 8) * (RS * 2) + kb + b_coff;
            ldm_x2(bhi[nt], sb + OFF2_BHI + ro);
            ldm_x2(blo[nt], sb + OFF2_BLO + ro);
        }
#pragma unroll
        for (int mt = 0; mt < 2; mt++)
#pragma unroll
            for (int nt = 0; nt < 2; nt++) {
                mma16816(acc[mt][nt], ahi[mt], bhi[nt]);
                mma16816(acc[mt][nt], alo[mt], bhi[nt]);
                mma16816(acc[mt][nt], ahi[mt], blo[nt]);
            }
    }

#pragma unroll
    for (int mt = 0; mt < 2; mt++) {
        int r0 = rowBase + wm + mt * 16 + (lane >> 2);
        int r1 = r0 + 8;
#pragma unroll
        for (int nt = 0; nt < 2; nt++) {
            int cg = wn + nt * 8 + (lane & 3) * 2;
            if (cg < 16) {
                float bs0 = __ldg(&b2[cg]), bs1 = __ldg(&b2[cg + 1]);
                if (r0 < NN)
                    *reinterpret_cast<float2*>(out + (size_t)r0 * NC + cg) =
                        make_float2(acc[mt][nt][0] + bs0, acc[mt][nt][1] + bs1);
                if (r1 < NN)
                    *reinterpret_cast<float2*>(out + (size_t)r1 * NC + cg) =
                        make_float2(acc[mt][nt][2] + bs0, acc[mt][nt][3] + bs1);
            } else {
                int cd = cg - 16;
                if (r0 < NN)
                    *reinterpret_cast<float2*>(g_D + (size_t)r0 * NC + cd) =
                        make_float2(acc[mt][nt][0], acc[mt][nt][1]);
                if (r1 < NN)
                    *reinterpret_cast<float2*>(g_D + (size_t)r1 * NC + cd) =
                        make_float2(acc[mt][nt][2], acc[mt][nt][3]);
            }
        }
    }
}

// ---------------- layer-2 aggregate + add ----------------
__global__ void agg2_k(float* __restrict__ out) {
    int idx = blockIdx.x * blockDim.x + threadIdx.x;
    int node = idx >> 4;
    if (node >= NN) return;
    int dim = idx & 15;
    int beg = g_rowoff[node], end = g_rowoff[node + 1];
    float s = 0.f;
    int e = beg;
    for (; e + 4 <= end; e += 4) {
        int i0 = g_esrc[e], i1 = g_esrc[e + 1], i2 = g_esrc[e + 2], i3 = g_esrc[e + 3];
        float v0 = g_D[(size_t)i0 * NC + dim];
        float v1 = g_D[(size_t)i1 * NC + dim];
        float v2 = g_D[(size_t)i2 * NC + dim];
        float v3 = g_D[(size_t)i3 * NC + dim];
        s += (v0 + v1) + (v2 + v3);
    }
    for (; e < end; e++)
        s += g_D[(size_t)g_esrc[e] * NC + dim];
    float inv = 1.0f / fmaxf((float)(end - beg), 1.0f);
    out[(size_t)node * NC + dim] += s * inv;
}

// ---------------- launch ----------------
extern "C" void kernel_launch(void* const* d_in, const int* in_sizes, int n_in,
                              void* d_out, int out_size)
{
    const float* in_feat = (const float*)d_in[0];
    const void*  src     = d_in[1];
    const void*  dst     = d_in[2];
    const float* Wself1  = (const float*)d_in[3];
    const float* Wneigh1 = (const float*)d_in[4];
    const float* b1      = (const float*)d_in[5];
    const float* Wself2  = (const float*)d_in[6];
    const float* Wneigh2 = (const float*)d_in[7];
    const float* b2      = (const float*)d_in[8];
    float* out = (float*)d_out;

    static int smem_set = 0;
    if (!smem_set) {
        cudaFuncSetAttribute(gemm1_mma, cudaFuncAttributeMaxDynamicSharedMemorySize, SMEM_G1);
        cudaFuncSetAttribute(gemm2_mma, cudaFuncAttributeMaxDynamicSharedMemorySize, SMEM_G2);
        smem_set = 1;
    }

    // prep (zero + detect + weight conversion) + CSR build
    prep_k <<<NBLK, 256>>>((const int*)dst, Wself1, Wneigh1, Wself2, Wneigh2);
    count_k<<<(NE + 255) / 256, 256>>>(dst);
    scanA_k<<<NBLK, 256>>>();
    scanC_k<<<NBLK, 256>>>();
    fill_k <<<(NE + 255) / 256, 256>>>(src, dst);

    // layer 1: both projections in one kernel (X converted in-kernel)
    gemm1_mma<<<(NN + 127) / 128, 512, SMEM_G1>>>(in_feat, b1);

    // layer 1: aggregate + combine + relu -> bf16 hi/lo
    agg1_k<<<(NN * 32 + 255) / 256, 256>>>();

    // layer 2: projections (out self part + bias; g_D neigh part)
    gemm2_mma<<<(NN + 127) / 128, 256, SMEM_G2>>>(b2, out);

    // layer 2: aggregate + add
    agg2_k<<<(NN * 16 + 255) / 256, 256>>>(out);
}

// round 8
// speedup vs baseline: 2.3597x; 1.0566x over previous
#include <cuda_runtime.h>
#include <cuda_bf16.h>
#include <cstdint>

#define NN 50000
#define NE 800000
#define F 128
#define NC 16
#define NBLK 196   // 196*256 = 50176 >= NN

// ---------------- scratch (static device globals; no allocs) ----------------
__device__ float g_h1[(size_t)NN * F];    // gemm1 self-proj + b1 (pre-relu)
__device__ __nv_bfloat16 g_nbh[(size_t)NN * F];  // gemm1 neigh-proj (bf16)
__device__ float g_D [(size_t)NN * NC];   // h1@W_neigh2
__device__ int   g_deg[NN];
__device__ int   g_cur[NN];
__device__ int   g_rowoff[NN + 1];
__device__ int   g_esrc[NE];
__device__ int   g_part[NBLK * 256];
__device__ int   g_bsum[NBLK];
__device__ int   g_is64;
// bf16 hi/lo split operands
__device__ __nv_bfloat16 g_wThi[2 * F * F];   // layer1 [mat][n][k] = W[k][n]
__device__ __nv_bfloat16 g_wTlo[2 * F * F];
__device__ __nv_bfloat16 g_w2Thi[32 * F];     // layer2 cat [n][k] (n<16 self, else neigh)
__device__ __nv_bfloat16 g_w2Tlo[32 * F];
__device__ __nv_bfloat16 g_h1hi[(size_t)NN * F];  // relu(h1) hi/lo
__device__ __nv_bfloat16 g_h1lo[(size_t)NN * F];

// ---------------- helpers ----------------
__device__ __forceinline__ uint32_t smem_u32(const void* p) {
    uint32_t a;
    asm("{ .reg .u64 t; cvta.to.shared.u64 t, %1; cvt.u32.u64 %0, t; }"
        : "=r"(a) : "l"(p));
    return a;
}
__device__ __forceinline__ void ldm_x4(uint32_t* r, uint32_t addr) {
    asm volatile("ldmatrix.sync.aligned.m8n8.x4.shared.b16 {%0,%1,%2,%3}, [%4];"
                 : "=r"(r[0]), "=r"(r[1]), "=r"(r[2]), "=r"(r[3]) : "r"(addr));
}
__device__ __forceinline__ void ldm_x2(uint32_t* r, uint32_t addr) {
    asm volatile("ldmatrix.sync.aligned.m8n8.x2.shared.b16 {%0,%1}, [%2];"
                 : "=r"(r[0]), "=r"(r[1]) : "r"(addr));
}
__device__ __forceinline__ void mma16816(float* d, const uint32_t* a, const uint32_t* b) {
    asm volatile("mma.sync.aligned.m16n8k16.row.col.f32.bf16.bf16.f32 "
                 "{%0,%1,%2,%3}, {%4,%5,%6,%7}, {%8,%9}, {%0,%1,%2,%3};"
                 : "+f"(d[0]), "+f"(d[1]), "+f"(d[2]), "+f"(d[3])
                 : "r"(a[0]), "r"(a[1]), "r"(a[2]), "r"(a[3]), "r"(b[0]), "r"(b[1]));
}
__device__ __forceinline__ uint32_t pack_bf2(float a, float b) {
    __nv_bfloat162 t(__float2bfloat16(a), __float2bfloat16(b));
    return *reinterpret_cast<uint32_t*>(&t);
}

// -------- prep: zero deg/cur + dtype detect + weight conversions ------------
__global__ void prep_k(const int* __restrict__ dst32,
                       const float* __restrict__ Ws1, const float* __restrict__ Wn1,
                       const float* __restrict__ Ws2, const float* __restrict__ Wn2) {
    int i = blockIdx.x * blockDim.x + threadIdx.x;
    if (i < NN) { g_deg[i] = 0; g_cur[i] = 0; }
    if (i == 0) {
        int all_zero = 1;
        for (int j = 0; j < 256; j++)
            if (dst32[2 * j + 1] != 0) { all_zero = 0; break; }
        g_is64 = all_zero;
    }
    if (i < 2 * F * F) {                 // layer1: [mat][n][k] = W[k][n]
        int mat = i >> 14, n = (i >> 7) & 127, k = i & 127;
        float w = (mat == 0) ? Ws1[k * F + n] : Wn1[k * F + n];
        __nv_bfloat16 h = __float2bfloat16(w);
        g_wThi[i] = h;
        g_wTlo[i] = __float2bfloat16(w - __bfloat162float(h));
    } else if (i < 2 * F * F + 32 * F) { // layer2 cat: [n][k]
        int i2 = i - 2 * F * F;
        int n = i2 >> 7, k = i2 & 127;
        float w = (n < 16) ? Ws2[k * 16 + n] : Wn2[k * 16 + (n - 16)];
        __nv_bfloat16 h = __float2bfloat16(w);
        g_w2Thi[i2] = h;
        g_w2Tlo[i2] = __float2bfloat16(w - __bfloat162float(h));
    }
}
__device__ __forceinline__ int load_idx(const void* p, int i) {
    if (g_is64) return (int)((const long long*)p)[i];
    return ((const int*)p)[i];
}

// ---------------- CSR build ----------------
__global__ void count_k(const void* __restrict__ dst) {
    int i = blockIdx.x * blockDim.x + threadIdx.x;
    if (i < NE) {
        int d = load_idx(dst, i);
        if (d >= 0 && d < NN) atomicAdd(&g_deg[d], 1);
    }
}
__global__ void scanA_k() {
    __shared__ int sh[256];
    int t = threadIdx.x, i = blockIdx.x * 256 + t;
    int v = (i < NN) ? g_deg[i] : 0;
    sh[t] = v;
    __syncthreads();
#pragma unroll
    for (int off = 1; off < 256; off <<= 1) {
        int u = (t >= off) ? sh[t - off] : 0;
        __syncthreads();
        sh[t] += u;
        __syncthreads();
    }
    g_part[i] = sh[t];
    if (t == 255) g_bsum[blockIdx.x] = sh[255];
}
// rowoff[i+1] = part[i] + sum(bsum[0..blk-1])
__global__ void scanC_k() {
    __shared__ int red[256];
    int t = threadIdx.x, b = blockIdx.x;
    red[t] = (t < b) ? g_bsum[t] : 0;
    __syncthreads();
#pragma unroll
    for (int off = 128; off >= 1; off >>= 1) {
        if (t < off) red[t] += red[t + off];
        __syncthreads();
    }
    int prefix = red[0];
    int i = b * 256 + t;
    if (i < NN) {
        g_rowoff[i + 1] = g_part[i] + prefix;
        if (i == 0) g_rowoff[0] = 0;
    }
}
__global__ void fill_k(const void* __restrict__ src, const void* __restrict__ dst) {
    int i = blockIdx.x * blockDim.x + threadIdx.x;
    if (i < NE) {
        int d = load_idx(dst, i);
        int s = load_idx(src, i);
        if (d < 0 || d >= NN || s < 0 || s >= NN) return;
        int pos = atomicAdd(&g_cur[d], 1);
        int off = g_rowoff[d] + pos;
        if (off < NE) g_esrc[off] = s;
    }
}

// ------- layer-1 GEMM: one CTA does BOTH projections (N = 256) --------------
#define RS 136                       // smem row stride in bf16 (272 bytes)
#define TILE_B (128 * RS * 2)        // 34816 bytes
#define OFF_AHI 0
#define OFF_ALO (TILE_B)
#define OFF_BHI (2 * TILE_B)         // 256 rows (mat0 then mat1)
#define OFF_BLO (4 * TILE_B)
#define SMEM_G1 (6 * TILE_B)         // 208896 B

__global__ void __launch_bounds__(512, 1)
gemm1_mma(const float* __restrict__ X, const float* __restrict__ b1) {
    extern __shared__ char smem[];
    uint32_t sb = smem_u32(smem);
    int tid = threadIdx.x, wid = tid >> 5, lane = tid & 31;
    int rowBase = blockIdx.x * 128;

    // stage A (fp32 -> bf16 hi/lo in flight)
    for (int i = tid; i < 128 * 16; i += 512) {
        int r = i >> 4, cc = i & 15;
        uint32_t so = (uint32_t)r * (RS * 2) + cc * 16;
        int gr = rowBase + r;
        float v[8] = {0.f, 0.f, 0.f, 0.f, 0.f, 0.f, 0.f, 0.f};
        if (gr < NN) {
            const float4* xp = reinterpret_cast<const float4*>(X + (size_t)gr * F + cc * 8);
            float4 f0 = xp[0], f1 = xp[1];
            v[0] = f0.x; v[1] = f0.y; v[2] = f0.z; v[3] = f0.w;
            v[4] = f1.x; v[5] = f1.y; v[6] = f1.z; v[7] = f1.w;
        }
        float hf[8], lf[8];
#pragma unroll
        for (int j = 0; j < 8; j++) {
            __nv_bfloat16 h = __float2bfloat16(v[j]);
            hf[j] = __bfloat162float(h);
            lf[j] = v[j] - hf[j];
        }
        uint4 uh = make_uint4(pack_bf2(hf[0], hf[1]), pack_bf2(hf[2], hf[3]),
                              pack_bf2(hf[4], hf[5]), pack_bf2(hf[6], hf[7]));
        uint4 ul = make_uint4(pack_bf2(lf[0], lf[1]), pack_bf2(lf[2], lf[3]),
                              pack_bf2(lf[4], lf[5]), pack_bf2(lf[6], lf[7]));
        *reinterpret_cast<uint4*>(smem + OFF_AHI + so) = uh;
        *reinterpret_cast<uint4*>(smem + OFF_ALO + so) = ul;
    }
    // stage B: 256 rows of W^T (mat0 rows 0-127, mat1 rows 128-255)
    for (int i = tid; i < 256 * 16; i += 512) {
        int r = i >> 4, cc = i & 15;
        uint32_t so = (uint32_t)r * (RS * 2) + cc * 16;
        *reinterpret_cast<uint4*>(smem + OFF_BHI + so) =
            reinterpret_cast<const uint4*>(g_wThi + (size_t)r * F)[cc];
        *reinterpret_cast<uint4*>(smem + OFF_BLO + so) =
            reinterpret_cast<const uint4*>(g_wTlo + (size_t)r * F)[cc];
    }
    __syncthreads();

    int wm = (wid & 3) * 32;       // warp rows
    int wn = (wid >> 2) * 64;      // warp cols (of 256)
    float acc[2][8][4];
#pragma unroll
    for (int mt = 0; mt < 2; mt++)
#pragma unroll
        for (int nt = 0; nt < 8; nt++)
#pragma unroll
            for (int e = 0; e < 4; e++) acc[mt][nt][e] = 0.f;

    uint32_t a_row = wm + (lane & 15);
    uint32_t a_coff = (lane >> 4) * 16;
    uint32_t b_row = wn + (lane & 7);
    uint32_t b_coff = ((lane >> 3) & 1) * 16;

#pragma unroll
    for (int ks = 0; ks < 8; ks++) {
        uint32_t kb = ks * 32;
        uint32_t ahi[2][4], alo[2][4];
#pragma unroll
        for (int mt = 0; mt < 2; mt++) {
            uint32_t ro = (a_row + mt * 16) * (RS * 2) + kb + a_coff;
            ldm_x4(ahi[mt], sb + OFF_AHI + ro);
            ldm_x4(alo[mt], sb + OFF_ALO + ro);
        }
#pragma unroll
        for (int half = 0; half < 2; half++) {
            uint32_t bhi[4][2], blo[4][2];
#pragma unroll
            for (int q = 0; q < 4; q++) {
                int nt = half * 4 + q;
                uint32_t ro = (b_row + nt * 8) * (RS * 2) + kb + b_coff;
                ldm_x2(bhi[q], sb + OFF_BHI + ro);
                ldm_x2(blo[q], sb + OFF_BLO + ro);
            }
#pragma unroll
            for (int mt = 0; mt < 2; mt++)
#pragma unroll
                for (int q = 0; q < 4; q++) {
                    int nt = half * 4 + q;
                    mma16816(acc[mt][nt], ahi[mt], bhi[q]);
                    mma16816(acc[mt][nt], alo[mt], bhi[q]);
                    mma16816(acc[mt][nt], ahi[mt], blo[q]);
                }
        }
    }

#pragma unroll
    for (int mt = 0; mt < 2; mt++) {
        int r0 = rowBase + wm + mt * 16 + (lane >> 2);
        int r1 = r0 + 8;
#pragma unroll
        for (int nt = 0; nt < 8; nt++) {
            int c = wn + nt * 8 + (lane & 3) * 2;   // 0..255
            if (c < 128) {
                float bs0 = __ldg(&b1[c]), bs1 = __ldg(&b1[c + 1]);
                if (r0 < NN)
                    *reinterpret_cast<float2*>(g_h1 + (size_t)r0 * F + c) =
                        make_float2(acc[mt][nt][0] + bs0, acc[mt][nt][1] + bs1);
                if (r1 < NN)
                    *reinterpret_cast<float2*>(g_h1 + (size_t)r1 * F + c) =
                        make_float2(acc[mt][nt][2] + bs0, acc[mt][nt][3] + bs1);
            } else {
                int cc = c - 128;
                if (r0 < NN)
                    *reinterpret_cast<uint32_t*>(g_nbh + (size_t)r0 * F + cc) =
                        pack_bf2(acc[mt][nt][0], acc[mt][nt][1]);
                if (r1 < NN)
                    *reinterpret_cast<uint32_t*>(g_nbh + (size_t)r1 * F + cc) =
                        pack_bf2(acc[mt][nt][2], acc[mt][nt][3]);
            }
        }
    }
}

// ------- layer-1 aggregate (bf16 gather) + combine + relu -> bf16 hi/lo -----
__global__ void agg1_k() {
    int node = (blockIdx.x * blockDim.x + threadIdx.x) >> 5;
    if (node >= NN) return;
    int lane = threadIdx.x & 31;
    int beg = g_rowoff[node], end = g_rowoff[node + 1];
    float s0 = 0.f, s1 = 0.f, s2 = 0.f, s3 = 0.f;
    int e = beg;
    for (; e + 4 <= end; e += 4) {
        int i0 = g_esrc[e], i1 = g_esrc[e + 1], i2 = g_esrc[e + 2], i3 = g_esrc[e + 3];
        uint2 u0 = reinterpret_cast<const uint2*>(g_nbh + (size_t)i0 * F)[lane];
        uint2 u1 = reinterpret_cast<const uint2*>(g_nbh + (size_t)i1 * F)[lane];
        uint2 u2 = reinterpret_cast<const uint2*>(g_nbh + (size_t)i2 * F)[lane];
        uint2 u3 = reinterpret_cast<const uint2*>(g_nbh + (size_t)i3 * F)[lane];
#pragma unroll
        for (int q = 0; q < 4; q++) {
            uint2 u = (q == 0) ? u0 : (q == 1) ? u1 : (q == 2) ? u2 : u3;
            float2 a = __bfloat1622float2(*reinterpret_cast<__nv_bfloat162*>(&u.x));
            float2 b = __bfloat1622float2(*reinterpret_cast<__nv_bfloat162*>(&u.y));
            s0 += a.x; s1 += a.y; s2 += b.x; s3 += b.y;
        }
    }
    for (; e < end; e++) {
        uint2 u = reinterpret_cast<const uint2*>(g_nbh + (size_t)g_esrc[e] * F)[lane];
        float2 a = __bfloat1622float2(*reinterpret_cast<__nv_bfloat162*>(&u.x));
        float2 b = __bfloat1622float2(*reinterpret_cast<__nv_bfloat162*>(&u.y));
        s0 += a.x; s1 += a.y; s2 += b.x; s3 += b.y;
    }
    float inv = 1.0f / fmaxf((float)(end - beg), 1.0f);
    float4 a = reinterpret_cast<const float4*>(g_h1 + (size_t)node * F)[lane];
    float r0 = fmaxf(a.x + s0 * inv, 0.f);
    float r1 = fmaxf(a.y + s1 * inv, 0.f);
    float r2 = fmaxf(a.z + s2 * inv, 0.f);
    float r3 = fmaxf(a.w + s3 * inv, 0.f);
    float h0 = __bfloat162float(__float2bfloat16(r0));
    float h1 = __bfloat162float(__float2bfloat16(r1));
    float h2 = __bfloat162float(__float2bfloat16(r2));
    float h3 = __bfloat162float(__float2bfloat16(r3));
    uint2 uh = make_uint2(pack_bf2(h0, h1), pack_bf2(h2, h3));
    uint2 ul = make_uint2(pack_bf2(r0 - h0, r1 - h1), pack_bf2(r2 - h2, r3 - h3));
    reinterpret_cast<uint2*>(g_h1hi + (size_t)node * F)[lane] = uh;
    reinterpret_cast<uint2*>(g_h1lo + (size_t)node * F)[lane] = ul;
}

// ---------------- layer-2 GEMM (mma.sync, N=32 = [self|neigh]) --------------
#define B2_B (32 * RS * 2)
#define OFF2_AHI 0
#define OFF2_ALO (TILE_B)
#define OFF2_BHI (2 * TILE_B)
#define OFF2_BLO (2 * TILE_B + B2_B)
#define SMEM_G2 (2 * TILE_B + 2 * B2_B)

__global__ void __launch_bounds__(256, 1)
gemm2_mma(const float* __restrict__ b2, float* __restrict__ out) {
    extern __shared__ char smem[];
    uint32_t sb = smem_u32(smem);
    int tid = threadIdx.x, wid = tid >> 5, lane = tid & 31;
    int rowBase = blockIdx.x * 128;

    for (int i = tid; i < 128 * 16; i += 256) {
        int r = i >> 4, cc = i & 15;
        uint32_t so = (uint32_t)r * (RS * 2) + cc * 16;
        int gr = rowBase + r;
        uint4 vh = make_uint4(0, 0, 0, 0), vl = make_uint4(0, 0, 0, 0);
        if (gr < NN) {
            vh = reinterpret_cast<const uint4*>(g_h1hi + (size_t)gr * F)[cc];
            vl = reinterpret_cast<const uint4*>(g_h1lo + (size_t)gr * F)[cc];
        }
        *reinterpret_cast<uint4*>(smem + OFF2_AHI + so) = vh;
        *reinterpret_cast<uint4*>(smem + OFF2_ALO + so) = vl;
    }
    for (int i = tid; i < 32 * 16; i += 256) {
        int r = i >> 4, cc = i & 15;
        uint32_t so = (uint32_t)r * (RS * 2) + cc * 16;
        *reinterpret_cast<uint4*>(smem + OFF2_BHI + so) =
            reinterpret_cast<const uint4*>(g_w2Thi + (size_t)r * F)[cc];
        *reinterpret_cast<uint4*>(smem + OFF2_BLO + so) =
            reinterpret_cast<const uint4*>(g_w2Tlo + (size_t)r * F)[cc];
    }
    __syncthreads();

    int wm = (wid & 3) * 32, wn = (wid >> 2) * 16;
    float acc[2][2][4];
#pragma unroll
    for (int mt = 0; mt < 2; mt++)
#pragma unroll
        for (int nt = 0; nt < 2; nt++)
#pragma unroll
            for (int e = 0; e < 4; e++) acc[mt][nt][e] = 0.f;

    uint32_t a_row = wm + (lane & 15);
    uint32_t a_coff = (lane >> 4) * 16;
    uint32_t b_row = wn + (lane & 7);
    uint32_t b_coff = ((lane >> 3) & 1) * 16;

#pragma unroll
    for (int ks = 0; ks < 8; ks++) {
        uint32_t kb = ks * 32;
        uint32_t ahi[2][4], alo[2][4], bhi[2][2], blo[2][2];
#pragma unroll
        for (int mt = 0; mt < 2; mt++) {
            uint32_t ro = (a_row + mt * 16) * (RS * 2) + kb + a_coff;
            ldm_x4(ahi[mt], sb + OFF2_AHI + ro);
            ldm_x4(alo[mt], sb + OFF2_ALO + ro);
        }
#pragma unroll
        for (int nt = 0; nt < 2; nt++) {
            uint32_t ro = (b_row + nt * 8) * (RS * 2) + kb + b_coff;
            ldm_x2(bhi[nt], sb + OFF2_BHI + ro);
            ldm_x2(blo[nt], sb + OFF2_BLO + ro);
        }
#pragma unroll
        for (int mt = 0; mt < 2; mt++)
#pragma unroll
            for (int nt = 0; nt < 2; nt++) {
                mma16816(acc[mt][nt], ahi[mt], bhi[nt]);
                mma16816(acc[mt][nt], alo[mt], bhi[nt]);
                mma16816(acc[mt][nt], ahi[mt], blo[nt]);
            }
    }

#pragma unroll
    for (int mt = 0; mt < 2; mt++) {
        int r0 = rowBase + wm + mt * 16 + (lane >> 2);
        int r1 = r0 + 8;
#pragma unroll
        for (int nt = 0; nt < 2; nt++) {
            int cg = wn + nt * 8 + (lane & 3) * 2;
            if (cg < 16) {
                float bs0 = __ldg(&b2[cg]), bs1 = __ldg(&b2[cg + 1]);
                if (r0 < NN)
                    *reinterpret_cast<float2*>(out + (size_t)r0 * NC + cg) =
                        make_float2(acc[mt][nt][0] + bs0, acc[mt][nt][1] + bs1);
                if (r1 < NN)
                    *reinterpret_cast<float2*>(out + (size_t)r1 * NC + cg) =
                        make_float2(acc[mt][nt][2] + bs0, acc[mt][nt][3] + bs1);
            } else {
                int cd = cg - 16;
                if (r0 < NN)
                    *reinterpret_cast<float2*>(g_D + (size_t)r0 * NC + cd) =
                        make_float2(acc[mt][nt][0], acc[mt][nt][1]);
                if (r1 < NN)
                    *reinterpret_cast<float2*>(g_D + (size_t)r1 * NC + cd) =
                        make_float2(acc[mt][nt][2], acc[mt][nt][3]);
            }
        }
    }
}

// ---------------- layer-2 aggregate + add ----------------
__global__ void agg2_k(float* __restrict__ out) {
    int idx = blockIdx.x * blockDim.x + threadIdx.x;
    int node = idx >> 4;
    if (node >= NN) return;
    int dim = idx & 15;
    int beg = g_rowoff[node], end = g_rowoff[node + 1];
    float s = 0.f;
    int e = beg;
    for (; e + 4 <= end; e += 4) {
        int i0 = g_esrc[e], i1 = g_esrc[e + 1], i2 = g_esrc[e + 2], i3 = g_esrc[e + 3];
        float v0 = g_D[(size_t)i0 * NC + dim];
        float v1 = g_D[(size_t)i1 * NC + dim];
        float v2 = g_D[(size_t)i2 * NC + dim];
        float v3 = g_D[(size_t)i3 * NC + dim];
        s += (v0 + v1) + (v2 + v3);
    }
    for (; e < end; e++)
        s += g_D[(size_t)g_esrc[e] * NC + dim];
    float inv = 1.0f / fmaxf((float)(end - beg), 1.0f);
    out[(size_t)node * NC + dim] += s * inv;
}

// ---------------- launch ----------------
extern "C" void kernel_launch(void* const* d_in, const int* in_sizes, int n_in,
                              void* d_out, int out_size)
{
    const float* in_feat = (const float*)d_in[0];
    const void*  src     = d_in[1];
    const void*  dst     = d_in[2];
    const float* Wself1  = (const float*)d_in[3];
    const float* Wneigh1 = (const float*)d_in[4];
    const float* b1      = (const float*)d_in[5];
    const float* Wself2  = (const float*)d_in[6];
    const float* Wneigh2 = (const float*)d_in[7];
    const float* b2      = (const float*)d_in[8];
    float* out = (float*)d_out;

    static int smem_set = 0;
    if (!smem_set) {
        cudaFuncSetAttribute(gemm1_mma, cudaFuncAttributeMaxDynamicSharedMemorySize, SMEM_G1);
        cudaFuncSetAttribute(gemm2_mma, cudaFuncAttributeMaxDynamicSharedMemorySize, SMEM_G2);
        smem_set = 1;
    }

    // prep (zero + detect + weight conversion) + CSR build
    prep_k <<<NBLK, 256>>>((const int*)dst, Wself1, Wneigh1, Wself2, Wneigh2);
    count_k<<<(NE + 255) / 256, 256>>>(dst);
    scanA_k<<<NBLK, 256>>>();
    scanC_k<<<NBLK, 256>>>();
    fill_k <<<(NE + 255) / 256, 256>>>(src, dst);

    // layer 1: both projections in one kernel (X converted in-kernel)
    gemm1_mma<<<(NN + 127) / 128, 512, SMEM_G1>>>(in_feat, b1);

    // layer 1: aggregate (bf16 gather) + combine + relu -> bf16 hi/lo
    agg1_k<<<(NN * 32 + 255) / 256, 256>>>();

    // layer 2: projections (out self part + bias; g_D neigh part)
    gemm2_mma<<<(NN + 127) / 128, 256, SMEM_G2>>>(b2, out);

    // layer 2: aggregate + add
    agg2_k<<<(NN * 16 + 255) / 256, 256>>>(out);
}

// round 9
// speedup vs baseline: 2.5251x; 1.0701x over previous
#include <cuda_runtime.h>
#include <cuda_bf16.h>
#include <cstdint>

#define NN 50000
#define NE 800000
#define F 128
#define NC 16
#define NBLK 196   // 196*256 = 50176 >= NN

// ---------------- scratch (static device globals; no allocs) ----------------
__device__ float g_h1[(size_t)NN * F];    // gemm1 self-proj + b1 (pre-relu)
__device__ __nv_bfloat16 g_nbh[(size_t)NN * F];  // gemm1 neigh-proj (bf16)
__device__ float g_D [(size_t)NN * NC];   // h1@W_neigh2
__device__ int   g_deg[NN];
__device__ int   g_cur[NN];
__device__ int   g_rowoff[NN + 1];
__device__ int   g_esrc[NE];
__device__ int   g_part[NBLK * 256];
__device__ int   g_bsum[NBLK];
__device__ int   g_is64;
// bf16 hi/lo split operands
__device__ __nv_bfloat16 g_wThi[2 * F * F];   // layer1 [mat][n][k] = W[k][n]
__device__ __nv_bfloat16 g_wTlo[2 * F * F];
__device__ __nv_bfloat16 g_w2Thi[32 * F];     // layer2 cat [n][k]
__device__ __nv_bfloat16 g_w2Tlo[32 * F];
__device__ __nv_bfloat16 g_h1hi[(size_t)NN * F];  // relu(h1) hi/lo
__device__ __nv_bfloat16 g_h1lo[(size_t)NN * F];

// ---------------- helpers ----------------
__device__ __forceinline__ uint32_t smem_u32(const void* p) {
    uint32_t a;
    asm("{ .reg .u64 t; cvta.to.shared.u64 t, %1; cvt.u32.u64 %0, t; }"
        : "=r"(a) : "l"(p));
    return a;
}
__device__ __forceinline__ void ldm_x4(uint32_t* r, uint32_t addr) {
    asm volatile("ldmatrix.sync.aligned.m8n8.x4.shared.b16 {%0,%1,%2,%3}, [%4];"
                 : "=r"(r[0]), "=r"(r[1]), "=r"(r[2]), "=r"(r[3]) : "r"(addr));
}
__device__ __forceinline__ void ldm_x2(uint32_t* r, uint32_t addr) {
    asm volatile("ldmatrix.sync.aligned.m8n8.x2.shared.b16 {%0,%1}, [%2];"
                 : "=r"(r[0]), "=r"(r[1]) : "r"(addr));
}
__device__ __forceinline__ void mma16816(float* d, const uint32_t* a, const uint32_t* b) {
    asm volatile("mma.sync.aligned.m16n8k16.row.col.f32.bf16.bf16.f32 "
                 "{%0,%1,%2,%3}, {%4,%5,%6,%7}, {%8,%9}, {%0,%1,%2,%3};"
                 : "+f"(d[0]), "+f"(d[1]), "+f"(d[2]), "+f"(d[3])
                 : "r"(a[0]), "r"(a[1]), "r"(a[2]), "r"(a[3]), "r"(b[0]), "r"(b[1]));
}
__device__ __forceinline__ uint32_t pack_bf2(float a, float b) {
    __nv_bfloat162 t(__float2bfloat16(a), __float2bfloat16(b));
    return *reinterpret_cast<uint32_t*>(&t);
}

// -------- prep: zero deg/cur + dtype detect + weight conversions ------------
__global__ void prep_k(const int* __restrict__ dst32,
                       const float* __restrict__ Ws1, const float* __restrict__ Wn1,
                       const float* __restrict__ Ws2, const float* __restrict__ Wn2) {
    int i = blockIdx.x * blockDim.x + threadIdx.x;
    if (i < NN) { g_deg[i] = 0; g_cur[i] = 0; }
    if (i == 0) {
        int all_zero = 1;
        for (int j = 0; j < 256; j++)
            if (dst32[2 * j + 1] != 0) { all_zero = 0; break; }
        g_is64 = all_zero;
    }
    if (i < 2 * F * F) {                 // layer1: [mat][n][k] = W[k][n]
        int mat = i >> 14, n = (i >> 7) & 127, k = i & 127;
        float w = (mat == 0) ? Ws1[k * F + n] : Wn1[k * F + n];
        __nv_bfloat16 h = __float2bfloat16(w);
        g_wThi[i] = h;
        g_wTlo[i] = __float2bfloat16(w - __bfloat162float(h));
    } else if (i < 2 * F * F + 32 * F) { // layer2 cat: [n][k]
        int i2 = i - 2 * F * F;
        int n = i2 >> 7, k = i2 & 127;
        float w = (n < 16) ? Ws2[k * 16 + n] : Wn2[k * 16 + (n - 16)];
        __nv_bfloat16 h = __float2bfloat16(w);
        g_w2Thi[i2] = h;
        g_w2Tlo[i2] = __float2bfloat16(w - __bfloat162float(h));
    }
}
__device__ __forceinline__ int load_idx(const void* p, int i) {
    if (g_is64) return (int)((const long long*)p)[i];
    return ((const int*)p)[i];
}

// ---------------- CSR build ----------------
__global__ void count_k(const void* __restrict__ dst) {
    int i = blockIdx.x * blockDim.x + threadIdx.x;
    if (i < NE) {
        int d = load_idx(dst, i);
        if (d >= 0 && d < NN) atomicAdd(&g_deg[d], 1);
    }
}
__global__ void scanA_k() {
    __shared__ int sh[256];
    int t = threadIdx.x, i = blockIdx.x * 256 + t;
    int v = (i < NN) ? g_deg[i] : 0;
    sh[t] = v;
    __syncthreads();
#pragma unroll
    for (int off = 1; off < 256; off <<= 1) {
        int u = (t >= off) ? sh[t - off] : 0;
        __syncthreads();
        sh[t] += u;
        __syncthreads();
    }
    g_part[i] = sh[t];
    if (t == 255) g_bsum[blockIdx.x] = sh[255];
}
__global__ void scanC_k() {
    __shared__ int red[256];
    int t = threadIdx.x, b = blockIdx.x;
    red[t] = (t < b) ? g_bsum[t] : 0;
    __syncthreads();
#pragma unroll
    for (int off = 128; off >= 1; off >>= 1) {
        if (t < off) red[t] += red[t + off];
        __syncthreads();
    }
    int prefix = red[0];
    int i = b * 256 + t;
    if (i < NN) {
        g_rowoff[i + 1] = g_part[i] + prefix;
        if (i == 0) g_rowoff[0] = 0;
    }
}
__global__ void fill_k(const void* __restrict__ src, const void* __restrict__ dst) {
    int i = blockIdx.x * blockDim.x + threadIdx.x;
    if (i < NE) {
        int d = load_idx(dst, i);
        int s = load_idx(src, i);
        if (d < 0 || d >= NN || s < 0 || s >= NN) return;
        int pos = atomicAdd(&g_cur[d], 1);
        int off = g_rowoff[d] + pos;
        if (off < NE) g_esrc[off] = s;
    }
}

// ------- layer-1 GEMM: one CTA does BOTH projections (N = 256) --------------
#define RS 136                       // smem row stride in bf16 (272 bytes)
#define TILE_B (128 * RS * 2)        // 34816 bytes
#define OFF_AHI 0
#define OFF_ALO (TILE_B)
#define OFF_BHI (2 * TILE_B)
#define OFF_BLO (4 * TILE_B)
#define SMEM_G1 (6 * TILE_B)

__global__ void __launch_bounds__(512, 1)
gemm1_mma(const float* __restrict__ X, const float* __restrict__ b1) {
    extern __shared__ char smem[];
    uint32_t sb = smem_u32(smem);
    int tid = threadIdx.x, wid = tid >> 5, lane = tid & 31;
    int rowBase = blockIdx.x * 128;

    for (int i = tid; i < 128 * 16; i += 512) {
        int r = i >> 4, cc = i & 15;
        uint32_t so = (uint32_t)r * (RS * 2) + cc * 16;
        int gr = rowBase + r;
        float v[8] = {0.f, 0.f, 0.f, 0.f, 0.f, 0.f, 0.f, 0.f};
        if (gr < NN) {
            const float4* xp = reinterpret_cast<const float4*>(X + (size_t)gr * F + cc * 8);
            float4 f0 = xp[0], f1 = xp[1];
            v[0] = f0.x; v[1] = f0.y; v[2] = f0.z; v[3] = f0.w;
            v[4] = f1.x; v[5] = f1.y; v[6] = f1.z; v[7] = f1.w;
        }
        float hf[8], lf[8];
#pragma unroll
        for (int j = 0; j < 8; j++) {
            __nv_bfloat16 h = __float2bfloat16(v[j]);
            hf[j] = __bfloat162float(h);
            lf[j] = v[j] - hf[j];
        }
        uint4 uh = make_uint4(pack_bf2(hf[0], hf[1]), pack_bf2(hf[2], hf[3]),
                              pack_bf2(hf[4], hf[5]), pack_bf2(hf[6], hf[7]));
        uint4 ul = make_uint4(pack_bf2(lf[0], lf[1]), pack_bf2(lf[2], lf[3]),
                              pack_bf2(lf[4], lf[5]), pack_bf2(lf[6], lf[7]));
        *reinterpret_cast<uint4*>(smem + OFF_AHI + so) = uh;
        *reinterpret_cast<uint4*>(smem + OFF_ALO + so) = ul;
    }
    for (int i = tid; i < 256 * 16; i += 512) {
        int r = i >> 4, cc = i & 15;
        uint32_t so = (uint32_t)r * (RS * 2) + cc * 16;
        *reinterpret_cast<uint4*>(smem + OFF_BHI + so) =
            reinterpret_cast<const uint4*>(g_wThi + (size_t)r * F)[cc];
        *reinterpret_cast<uint4*>(smem + OFF_BLO + so) =
            reinterpret_cast<const uint4*>(g_wTlo + (size_t)r * F)[cc];
    }
    __syncthreads();

    int wm = (wid & 3) * 32;
    int wn = (wid >> 2) * 64;
    float acc[2][8][4];
#pragma unroll
    for (int mt = 0; mt < 2; mt++)
#pragma unroll
        for (int nt = 0; nt < 8; nt++)
#pragma unroll
            for (int e = 0; e < 4; e++) acc[mt][nt][e] = 0.f;

    uint32_t a_row = wm + (lane & 15);
    uint32_t a_coff = (lane >> 4) * 16;
    uint32_t b_row = wn + (lane & 7);
    uint32_t b_coff = ((lane >> 3) & 1) * 16;

#pragma unroll
    for (int ks = 0; ks < 8; ks++) {
        uint32_t kb = ks * 32;
        uint32_t ahi[2][4], alo[2][4];
#pragma unroll
        for (int mt = 0; mt < 2; mt++) {
            uint32_t ro = (a_row + mt * 16) * (RS * 2) + kb + a_coff;
            ldm_x4(ahi[mt], sb + OFF_AHI + ro);
            ldm_x4(alo[mt], sb + OFF_ALO + ro);
        }
#pragma unroll
        for (int half = 0; half < 2; half++) {
            uint32_t bhi[4][2], blo[4][2];
#pragma unroll
            for (int q = 0; q < 4; q++) {
                int nt = half * 4 + q;
                uint32_t ro = (b_row + nt * 8) * (RS * 2) + kb + b_coff;
                ldm_x2(bhi[q], sb + OFF_BHI + ro);
                ldm_x2(blo[q], sb + OFF_BLO + ro);
            }
#pragma unroll
            for (int mt = 0; mt < 2; mt++)
#pragma unroll
                for (int q = 0; q < 4; q++) {
                    int nt = half * 4 + q;
                    mma16816(acc[mt][nt], ahi[mt], bhi[q]);
                    mma16816(acc[mt][nt], alo[mt], bhi[q]);
                    mma16816(acc[mt][nt], ahi[mt], blo[q]);
                }
        }
    }

#pragma unroll
    for (int mt = 0; mt < 2; mt++) {
        int r0 = rowBase + wm + mt * 16 + (lane >> 2);
        int r1 = r0 + 8;
#pragma unroll
        for (int nt = 0; nt < 8; nt++) {
            int c = wn + nt * 8 + (lane & 3) * 2;
            if (c < 128) {
                float bs0 = __ldg(&b1[c]), bs1 = __ldg(&b1[c + 1]);
                if (r0 < NN)
                    *reinterpret_cast<float2*>(g_h1 + (size_t)r0 * F + c) =
                        make_float2(acc[mt][nt][0] + bs0, acc[mt][nt][1] + bs1);
                if (r1 < NN)
                    *reinterpret_cast<float2*>(g_h1 + (size_t)r1 * F + c) =
                        make_float2(acc[mt][nt][2] + bs0, acc[mt][nt][3] + bs1);
            } else {
                int cc = c - 128;
                if (r0 < NN)
                    *reinterpret_cast<uint32_t*>(g_nbh + (size_t)r0 * F + cc) =
                        pack_bf2(acc[mt][nt][0], acc[mt][nt][1]);
                if (r1 < NN)
                    *reinterpret_cast<uint32_t*>(g_nbh + (size_t)r1 * F + cc) =
                        pack_bf2(acc[mt][nt][2], acc[mt][nt][3]);
            }
        }
    }
}

// ------- layer-1 aggregate (bf16 gather) + combine + relu -> bf16 hi/lo -----
__global__ void agg1_k() {
    int node = (blockIdx.x * blockDim.x + threadIdx.x) >> 5;
    if (node >= NN) return;
    int lane = threadIdx.x & 31;
    int beg = g_rowoff[node], end = g_rowoff[node + 1];
    float s0 = 0.f, s1 = 0.f, s2 = 0.f, s3 = 0.f;
    int e = beg;
    for (; e + 4 <= end; e += 4) {
        int i0 = g_esrc[e], i1 = g_esrc[e + 1], i2 = g_esrc[e + 2], i3 = g_esrc[e + 3];
        uint2 u0 = reinterpret_cast<const uint2*>(g_nbh + (size_t)i0 * F)[lane];
        uint2 u1 = reinterpret_cast<const uint2*>(g_nbh + (size_t)i1 * F)[lane];
        uint2 u2 = reinterpret_cast<const uint2*>(g_nbh + (size_t)i2 * F)[lane];
        uint2 u3 = reinterpret_cast<const uint2*>(g_nbh + (size_t)i3 * F)[lane];
#pragma unroll
        for (int q = 0; q < 4; q++) {
            uint2 u = (q == 0) ? u0 : (q == 1) ? u1 : (q == 2) ? u2 : u3;
            float2 a = __bfloat1622float2(*reinterpret_cast<__nv_bfloat162*>(&u.x));
            float2 b = __bfloat1622float2(*reinterpret_cast<__nv_bfloat162*>(&u.y));
            s0 += a.x; s1 += a.y; s2 += b.x; s3 += b.y;
        }
    }
    for (; e < end; e++) {
        uint2 u = reinterpret_cast<const uint2*>(g_nbh + (size_t)g_esrc[e] * F)[lane];
        float2 a = __bfloat1622float2(*reinterpret_cast<__nv_bfloat162*>(&u.x));
        float2 b = __bfloat1622float2(*reinterpret_cast<__nv_bfloat162*>(&u.y));
        s0 += a.x; s1 += a.y; s2 += b.x; s3 += b.y;
    }
    float inv = 1.0f / fmaxf((float)(end - beg), 1.0f);
    float4 a = reinterpret_cast<const float4*>(g_h1 + (size_t)node * F)[lane];
    float r0 = fmaxf(a.x + s0 * inv, 0.f);
    float r1 = fmaxf(a.y + s1 * inv, 0.f);
    float r2 = fmaxf(a.z + s2 * inv, 0.f);
    float r3 = fmaxf(a.w + s3 * inv, 0.f);
    float h0 = __bfloat162float(__float2bfloat16(r0));
    float h1 = __bfloat162float(__float2bfloat16(r1));
    float h2 = __bfloat162float(__float2bfloat16(r2));
    float h3 = __bfloat162float(__float2bfloat16(r3));
    uint2 uh = make_uint2(pack_bf2(h0, h1), pack_bf2(h2, h3));
    uint2 ul = make_uint2(pack_bf2(r0 - h0, r1 - h1), pack_bf2(r2 - h2, r3 - h3));
    reinterpret_cast<uint2*>(g_h1hi + (size_t)node * F)[lane] = uh;
    reinterpret_cast<uint2*>(g_h1lo + (size_t)node * F)[lane] = ul;
}

// ---------------- layer-2 GEMM (mma.sync, N=32 = [self|neigh]) --------------
#define B2_B (32 * RS * 2)
#define OFF2_AHI 0
#define OFF2_ALO (TILE_B)
#define OFF2_BHI (2 * TILE_B)
#define OFF2_BLO (2 * TILE_B + B2_B)
#define SMEM_G2 (2 * TILE_B + 2 * B2_B)

__global__ void __launch_bounds__(256, 1)
gemm2_mma(const float* __restrict__ b2, float* __restrict__ out) {
    extern __shared__ char smem[];
    uint32_t sb = smem_u32(smem);
    int tid = threadIdx.x, wid = tid >> 5, lane = tid & 31;
    int rowBase = blockIdx.x * 128;

    for (int i = tid; i < 128 * 16; i += 256) {
        int r = i >> 4, cc = i & 15;
        uint32_t so = (uint32_t)r * (RS * 2) + cc * 16;
        int gr = rowBase + r;
        uint4 vh = make_uint4(0, 0, 0, 0), vl = make_uint4(0, 0, 0, 0);
        if (gr < NN) {
            vh = reinterpret_cast<const uint4*>(g_h1hi + (size_t)gr * F)[cc];
            vl = reinterpret_cast<const uint4*>(g_h1lo + (size_t)gr * F)[cc];
        }
        *reinterpret_cast<uint4*>(smem + OFF2_AHI + so) = vh;
        *reinterpret_cast<uint4*>(smem + OFF2_ALO + so) = vl;
    }
    for (int i = tid; i < 32 * 16; i += 256) {
        int r = i >> 4, cc = i & 15;
        uint32_t so = (uint32_t)r * (RS * 2) + cc * 16;
        *reinterpret_cast<uint4*>(smem + OFF2_BHI + so) =
            reinterpret_cast<const uint4*>(g_w2Thi + (size_t)r * F)[cc];
        *reinterpret_cast<uint4*>(smem + OFF2_BLO + so) =
            reinterpret_cast<const uint4*>(g_w2Tlo + (size_t)r * F)[cc];
    }
    __syncthreads();

    int wm = (wid & 3) * 32, wn = (wid >> 2) * 16;
    float acc[2][2][4];
#pragma unroll
    for (int mt = 0; mt < 2; mt++)
#pragma unroll
        for (int nt = 0; nt < 2; nt++)
#pragma unroll
            for (int e = 0; e < 4; e++) acc[mt][nt][e] = 0.f;

    uint32_t a_row = wm + (lane & 15);
    uint32_t a_coff = (lane >> 4) * 16;
    uint32_t b_row = wn + (lane & 7);
    uint32_t b_coff = ((lane >> 3) & 1) * 16;

#pragma unroll
    for (int ks = 0; ks < 8; ks++) {
        uint32_t kb = ks * 32;
        uint32_t ahi[2][4], alo[2][4], bhi[2][2], blo[2][2];
#pragma unroll
        for (int mt = 0; mt < 2; mt++) {
            uint32_t ro = (a_row + mt * 16) * (RS * 2) + kb + a_coff;
            ldm_x4(ahi[mt], sb + OFF2_AHI + ro);
            ldm_x4(alo[mt], sb + OFF2_ALO + ro);
        }
#pragma unroll
        for (int nt = 0; nt < 2; nt++) {
            uint32_t ro = (b_row + nt * 8) * (RS * 2) + kb + b_coff;
            ldm_x2(bhi[nt], sb + OFF2_BHI + ro);
            ldm_x2(blo[nt], sb + OFF2_BLO + ro);
        }
#pragma unroll
        for (int mt = 0; mt < 2; mt++)
#pragma unroll
            for (int nt = 0; nt < 2; nt++) {
                mma16816(acc[mt][nt], ahi[mt], bhi[nt]);
                mma16816(acc[mt][nt], alo[mt], bhi[nt]);
                mma16816(acc[mt][nt], ahi[mt], blo[nt]);
            }
    }

#pragma unroll
    for (int mt = 0; mt < 2; mt++) {
        int r0 = rowBase + wm + mt * 16 + (lane >> 2);
        int r1 = r0 + 8;
#pragma unroll
        for (int nt = 0; nt < 2; nt++) {
            int cg = wn + nt * 8 + (lane & 3) * 2;
            if (cg < 16) {
                float bs0 = __ldg(&b2[cg]), bs1 = __ldg(&b2[cg + 1]);
                if (r0 < NN)
                    *reinterpret_cast<float2*>(out + (size_t)r0 * NC + cg) =
                        make_float2(acc[mt][nt][0] + bs0, acc[mt][nt][1] + bs1);
                if (r1 < NN)
                    *reinterpret_cast<float2*>(out + (size_t)r1 * NC + cg) =
                        make_float2(acc[mt][nt][2] + bs0, acc[mt][nt][3] + bs1);
            } else {
                int cd = cg - 16;
                if (r0 < NN)
                    *reinterpret_cast<float2*>(g_D + (size_t)r0 * NC + cd) =
                        make_float2(acc[mt][nt][0], acc[mt][nt][1]);
                if (r1 < NN)
                    *reinterpret_cast<float2*>(g_D + (size_t)r1 * NC + cd) =
                        make_float2(acc[mt][nt][2], acc[mt][nt][3]);
            }
        }
    }
}

// ---------------- layer-2 aggregate + add ----------------
__global__ void agg2_k(float* __restrict__ out) {
    int idx = blockIdx.x * blockDim.x + threadIdx.x;
    int node = idx >> 4;
    if (node >= NN) return;
    int dim = idx & 15;
    int beg = g_rowoff[node], end = g_rowoff[node + 1];
    float s = 0.f;
    int e = beg;
    for (; e + 4 <= end; e += 4) {
        int i0 = g_esrc[e], i1 = g_esrc[e + 1], i2 = g_esrc[e + 2], i3 = g_esrc[e + 3];
        float v0 = g_D[(size_t)i0 * NC + dim];
        float v1 = g_D[(size_t)i1 * NC + dim];
        float v2 = g_D[(size_t)i2 * NC + dim];
        float v3 = g_D[(size_t)i3 * NC + dim];
        s += (v0 + v1) + (v2 + v3);
    }
    for (; e < end; e++)
        s += g_D[(size_t)g_esrc[e] * NC + dim];
    float inv = 1.0f / fmaxf((float)(end - beg), 1.0f);
    out[(size_t)node * NC + dim] += s * inv;
}

// ---------------- launch (two-stream overlap: CSR || gemm1) ----------------
extern "C" void kernel_launch(void* const* d_in, const int* in_sizes, int n_in,
                              void* d_out, int out_size)
{
    const float* in_feat = (const float*)d_in[0];
    const void*  src     = d_in[1];
    const void*  dst     = d_in[2];
    const float* Wself1  = (const float*)d_in[3];
    const float* Wneigh1 = (const float*)d_in[4];
    const float* b1      = (const float*)d_in[5];
    const float* Wself2  = (const float*)d_in[6];
    const float* Wneigh2 = (const float*)d_in[7];
    const float* b2      = (const float*)d_in[8];
    float* out = (float*)d_out;

    static cudaStream_t s2 = nullptr;
    static cudaEvent_t evFork = nullptr, evJoin = nullptr;
    if (!s2) {
        cudaFuncSetAttribute(gemm1_mma, cudaFuncAttributeMaxDynamicSharedMemorySize, SMEM_G1);
        cudaFuncSetAttribute(gemm2_mma, cudaFuncAttributeMaxDynamicSharedMemorySize, SMEM_G2);
        cudaStreamCreateWithFlags(&s2, cudaStreamNonBlocking);
        cudaEventCreateWithFlags(&evFork, cudaEventDisableTiming);
        cudaEventCreateWithFlags(&evJoin, cudaEventDisableTiming);
    }

    // prep on main stream (zero + detect + weight conversion)
    prep_k<<<NBLK, 256>>>((const int*)dst, Wself1, Wneigh1, Wself2, Wneigh2);

    // fork: CSR chain on s2, gemm1 on main
    cudaEventRecord(evFork, 0);
    cudaStreamWaitEvent(s2, evFork, 0);

    count_k<<<(NE + 255) / 256, 256, 0, s2>>>(dst);
    scanA_k<<<NBLK, 256, 0, s2>>>();
    scanC_k<<<NBLK, 256, 0, s2>>>();
    fill_k <<<(NE + 255) / 256, 256, 0, s2>>>(src, dst);
    cudaEventRecord(evJoin, s2);

    gemm1_mma<<<(NN + 127) / 128, 512, SMEM_G1>>>(in_feat, b1);

    // join: agg1 needs both fill_k (s2) and gemm1 (main)
    cudaStreamWaitEvent(0, evJoin, 0);

    agg1_k<<<(NN * 32 + 255) / 256, 256>>>();
    gemm2_mma<<<(NN + 127) / 128, 256, SMEM_G2>>>(b2, out);
    agg2_k<<<(NN * 16 + 255) / 256, 256>>>(out);
}